// round 12
// baseline (speedup 1.0000x reference)
#include <cuda_runtime.h>
#include <cuda_fp16.h>
#include <mma.h>
#include <math.h>
#include <stdint.h>

using namespace nvcuda;

#define BATCH 2
#define SEQ 2048
#define DIM 1024
#define NH 16
#define HD 64
#define DH 32
#define MTOT (BATCH*SEQ)   // 4096
#define SCALE 0.125f

// ---------------- device scratch (no allocation allowed) -------------------
__device__ float g_sin[SEQ*DH], g_cos[SEQ*DH];
__device__ __half g_Xh[MTOT*DIM];
__device__ __half g_Wh[3][DIM*DIM];
__device__ __half g_Qh[MTOT*DIM];
__device__ __half g_Kh[MTOT*DIM];
__device__ __half g_Vh[MTOT*DIM];

// ---------------- cp.async helpers -----------------------------------------
#define CP_ASYNC16(dst_u32, src_ptr) \
    asm volatile("cp.async.cg.shared.global [%0], [%1], 16;" \
                 :: "r"(dst_u32), "l"(src_ptr) : "memory")
#define CP_COMMIT() asm volatile("cp.async.commit_group;" ::: "memory")
#define CP_WAIT0()  asm volatile("cp.async.wait_group 0;" ::: "memory")

// ---------------------------------------------------------------------------
// RoPE tables in double precision (safe at large angles)
// ---------------------------------------------------------------------------
__global__ void rope_table_kernel() {
    int idx = blockIdx.x * blockDim.x + threadIdx.x;
    if (idx >= SEQ * DH) return;
    int s = idx / DH, i = idx % DH;
    double ang = (double)s * pow(10000.0, -((double)i) / (double)DH);
    g_sin[idx] = (float)sin(ang);
    g_cos[idx] = (float)cos(ang);
}

// ---------------------------------------------------------------------------
// Convert fp32 -> single fp16.  which 0: X; 1..3: W[which-1]
// ---------------------------------------------------------------------------
__global__ void split_kernel(const float* __restrict__ src, int which, int n2) {
    int i = blockIdx.x * blockDim.x + threadIdx.x;
    if (i >= n2) return;
    float2 x = ((const float2*)src)[i];
    __half2 hh;
    hh.x = __float2half(x.x);
    hh.y = __float2half(x.y);
    __half* dst = (which == 0) ? g_Xh : g_Wh[which - 1];
    ((__half2*)dst)[i] = hh;
}

// ---------------------------------------------------------------------------
// Fused WMMA GEMM + epilogue: Q/K/V[which] = rope(X @ W^T + b) as fp16
// [B,H,S,HD].  Single fp16 MMA, tile 128x128, 8 warps, k-chunk 64,
// cp.async DOUBLE-BUFFERED staging. Epilogue via dedicated fp32 smem.
// ---------------------------------------------------------------------------
#define PLD 72                        // fp16 staging ld
#define YLD 132                       // fp32 epilogue ld (128 + 4 pad)
#define STG_B (128 * PLD * 2)         // 18432: one matrix staging
#define BUF_B (2 * STG_B)             // 36864: A+B for one stage
#define G_STAGE (2 * BUF_B)           // 73728: double buffer
#define PROJ_SMEM (G_STAGE + 128 * YLD * 4)   // 73728 + 67584 = 141312

__global__ __launch_bounds__(256) void gemm_fused(
    const float* __restrict__ bq, const float* __restrict__ bk,
    const float* __restrict__ bv)
{
    extern __shared__ __align__(128) char smraw[];
    float* Ysh = (float*)(smraw + G_STAGE);   // dedicated, disjoint

    int tid = threadIdx.x, wid = tid >> 5;
    int n0 = blockIdx.x * 128, m0 = blockIdx.y * 128, which = blockIdx.z;

    const __half* Xp = g_Xh + (size_t)m0 * DIM;
    const __half* Wp = g_Wh[which] + (size_t)n0 * DIM;
    uint32_t sbase = (uint32_t)__cvta_generic_to_shared(smraw);

    // prefetch k-chunk 0 into buffer 0
    #pragma unroll
    for (int i = 0; i < 4; i++) {
        int idx = tid + i * 256;
        int row = idx >> 3, c8 = (idx & 7) * 8;
        CP_ASYNC16(sbase + (row * PLD + c8) * 2,         &Xp[row * DIM + c8]);
        CP_ASYNC16(sbase + STG_B + (row * PLD + c8) * 2, &Wp[row * DIM + c8]);
    }
    CP_COMMIT();

    wmma::fragment<wmma::accumulator, 16, 16, 16, float> c[4][2];
    #pragma unroll
    for (int i = 0; i < 4; i++)
        #pragma unroll
        for (int j = 0; j < 2; j++) wmma::fill_fragment(c[i][j], 0.f);

    int wm = (wid >> 2) * 64, wn = (wid & 3) * 32;

    for (int it = 0; it < DIM / 64; it++) {
        int cur = it & 1;
        __half* Ast = (__half*)(smraw + cur * BUF_B);
        __half* Bst = (__half*)(smraw + cur * BUF_B + STG_B);

        CP_WAIT0();
        __syncthreads();   // stage[cur] ready; stage[1-cur] free (used in it-1)

        if (it + 1 < DIM / 64) {
            int k0n = (it + 1) * 64;
            uint32_t nb = sbase + (1 - cur) * BUF_B;
            #pragma unroll
            for (int i = 0; i < 4; i++) {
                int idx = tid + i * 256;
                int row = idx >> 3, c8 = (idx & 7) * 8;
                CP_ASYNC16(nb + (row * PLD + c8) * 2,         &Xp[row * DIM + k0n + c8]);
                CP_ASYNC16(nb + STG_B + (row * PLD + c8) * 2, &Wp[row * DIM + k0n + c8]);
            }
            CP_COMMIT();
        }

        #pragma unroll
        for (int ks = 0; ks < 4; ks++) {
            wmma::fragment<wmma::matrix_a, 16, 16, 16, __half, wmma::row_major> af[4];
            wmma::fragment<wmma::matrix_b, 16, 16, 16, __half, wmma::col_major> bf[2];
            #pragma unroll
            for (int i = 0; i < 4; i++)
                wmma::load_matrix_sync(af[i], &Ast[(wm + 16 * i) * PLD + ks * 16], PLD);
            #pragma unroll
            for (int j = 0; j < 2; j++)
                wmma::load_matrix_sync(bf[j], &Bst[(wn + 16 * j) * PLD + ks * 16], PLD);
            #pragma unroll
            for (int i = 0; i < 4; i++)
                #pragma unroll
                for (int j = 0; j < 2; j++)
                    wmma::mma_sync(c[i][j], af[i], bf[j], c[i][j]);
        }
    }

    __syncthreads();
    #pragma unroll
    for (int i = 0; i < 4; i++)
        #pragma unroll
        for (int j = 0; j < 2; j++)
            wmma::store_matrix_sync(&Ysh[(wm + 16 * i) * YLD + wn + 16 * j],
                                    c[i][j], YLD, wmma::mem_row_major);
    __syncthreads();

    // Epilogue (verified finish logic, reading smem)
    const float* bias = (which == 0) ? bq : (which == 1) ? bk : bv;
    __half* dstp = (which == 0) ? g_Qh : (which == 1) ? g_Kh : g_Vh;
    #pragma unroll
    for (int it = 0; it < 8; it++) {
        int idx = tid + it * 256;        // 0..2047
        int q = idx & 7;
        int hh = (idx >> 3) & 1;
        int row = idx >> 4;              // 0..127
        int c0 = q * 4;
        int m = m0 + row, b = m / SEQ, s = m % SEQ;
        int h = (n0 >> 6) + hh;

        float o1[4], o2[4];
        #pragma unroll
        for (int t = 0; t < 4; t++) {
            o1[t] = Ysh[row * YLD + hh * 64 + c0 + t]      + bias[hh * 64 + n0 + c0 + t];
            o2[t] = Ysh[row * YLD + hh * 64 + c0 + DH + t] + bias[hh * 64 + n0 + c0 + DH + t];
        }
        if (which != 2) {
            #pragma unroll
            for (int t = 0; t < 4; t++) {
                float sn = g_sin[s * DH + c0 + t], cs = g_cos[s * DH + c0 + t];
                float a = o1[t], bb = o2[t];
                o1[t] = a * cs - bb * sn;
                o2[t] = a * sn + bb * cs;
            }
        }
        size_t base = ((size_t)(b * NH + h) * SEQ + s) * HD;
        #pragma unroll
        for (int half_i = 0; half_i < 2; half_i++) {
            float* o = half_i ? o2 : o1;
            size_t off = base + c0 + half_i * DH;
            __half2 v0, v1;
            v0.x = __float2half(o[0]); v0.y = __float2half(o[1]);
            v1.x = __float2half(o[2]); v1.y = __float2half(o[3]);
            *(__half2*)(dstp + off)     = v0;
            *(__half2*)(dstp + off + 2) = v1;
        }
    }
}

// ---------------------------------------------------------------------------
// WMMA flash attention: 128q x 64k tiles, 8 warps (4m x 2n), 256 threads.
// QK^T + P.V: single fp16 MMAs. cp.async double-buffered K/V prefetch.
// __expf softmax (MUFU.EX2 path — 5x cheaper than expf polynomial).
// ---------------------------------------------------------------------------
#define TQ 128
#define NT (SEQ / 64)
#define ALD 72      // fp16 smem ld
#define SLD 68      // fp32 smem ld
#define OFF_QH 0
#define OFF_K0 (OFF_QH + TQ*ALD*2)         // 18432
#define OFF_K1 (OFF_K0 + 64*ALD*2)         // 27648
#define OFF_V0 (OFF_K1 + 64*ALD*2)         // 36864
#define OFF_V1 (OFF_V0 + 64*ALD*2)         // 46080
#define OFF_PH (OFF_V1 + 64*ALD*2)         // 55296
#define OFF_S  (OFF_PH + TQ*ALD*2)         // 73728
#define OFF_L  (OFF_S + TQ*SLD*4)          // 108544
#define ATTN_SMEM (OFF_L + TQ*4)           // 109056

__global__ __launch_bounds__(256) void attn_wmma(float* __restrict__ out) {
    extern __shared__ __align__(128) char smraw[];
    __half* Qh_s = (__half*)(smraw + OFF_QH);
    __half* Ph_s = (__half*)(smraw + OFF_PH);
    float* Ssh = (float*)(smraw + OFF_S);
    float* Lsh = (float*)(smraw + OFF_L);

    int tid = threadIdx.x, wid = tid >> 5;
    int q0 = blockIdx.x * TQ, bh = blockIdx.y;
    int b = bh >> 4, h = bh & 15;

    const __half* Qp = g_Qh + ((size_t)bh * SEQ + q0) * HD;
    const __half* Kp = g_Kh + (size_t)bh * SEQ * HD;
    const __half* Vp = g_Vh + (size_t)bh * SEQ * HD;

    // load Q tile (128 rows x 64 cols fp16)
    #pragma unroll
    for (int i = 0; i < 4; i++) {
        int idx = tid + i * 256;
        int row = idx >> 3, c8 = (idx & 7) * 8;
        *(uint4*)&Qh_s[row * ALD + c8] = *(const uint4*)&Qp[row * HD + c8];
    }
    if (tid < TQ) Lsh[tid] = 0.f;

    // prefetch tile 0 K/V
    {
        int row = tid >> 3, c8 = (tid & 7) * 8;
        #pragma unroll
        for (int half_i = 0; half_i < 2; half_i++) {
            int r = row + half_i * 32;
            size_t g = (size_t)r * HD + c8;
            uint32_t kd = (uint32_t)__cvta_generic_to_shared(smraw + OFF_K0) + (r * ALD + c8) * 2;
            uint32_t vd = (uint32_t)__cvta_generic_to_shared(smraw + OFF_V0) + (r * ALD + c8) * 2;
            CP_ASYNC16(kd, &Kp[g]);
            CP_ASYNC16(vd, &Vp[g]);
        }
        CP_COMMIT();
    }

    int wm = (wid >> 1) * 32, wn = (wid & 1) * 32;
    wmma::fragment<wmma::accumulator, 16, 16, 16, float> ctx[2][2];
    #pragma unroll
    for (int i = 0; i < 2; i++)
        #pragma unroll
        for (int j = 0; j < 2; j++) wmma::fill_fragment(ctx[i][j], 0.f);

    for (int kt = 0; kt < NT; kt++) {
        int cur = kt & 1;
        __half* Kc = (__half*)(smraw + (cur ? OFF_K1 : OFF_K0));
        __half* Vc = (__half*)(smraw + (cur ? OFF_V1 : OFF_V0));

        CP_WAIT0();
        __syncthreads();

        if (kt + 1 < NT) {
            int nxt = 1 - cur;
            uint32_t kb = (uint32_t)__cvta_generic_to_shared(smraw + (nxt ? OFF_K1 : OFF_K0));
            uint32_t vb = (uint32_t)__cvta_generic_to_shared(smraw + (nxt ? OFF_V1 : OFF_V0));
            int row = tid >> 3, c8 = (tid & 7) * 8;
            #pragma unroll
            for (int half_i = 0; half_i < 2; half_i++) {
                int r = row + half_i * 32;
                size_t g = (size_t)((kt + 1) * 64 + r) * HD + c8;
                CP_ASYNC16(kb + (r * ALD + c8) * 2, &Kp[g]);
                CP_ASYNC16(vb + (r * ALD + c8) * 2, &Vp[g]);
            }
            CP_COMMIT();
        }

        // S = Q . K^T  (single fp16 MMA)
        wmma::fragment<wmma::accumulator, 16, 16, 16, float> sc[2][2];
        #pragma unroll
        for (int i = 0; i < 2; i++)
            #pragma unroll
            for (int j = 0; j < 2; j++) wmma::fill_fragment(sc[i][j], 0.f);
        #pragma unroll
        for (int ks = 0; ks < 4; ks++) {
            wmma::fragment<wmma::matrix_a, 16, 16, 16, __half, wmma::row_major> af[2];
            wmma::fragment<wmma::matrix_b, 16, 16, 16, __half, wmma::col_major> bf[2];
            #pragma unroll
            for (int i = 0; i < 2; i++)
                wmma::load_matrix_sync(af[i], &Qh_s[(wm + 16 * i) * ALD + 16 * ks], ALD);
            #pragma unroll
            for (int j = 0; j < 2; j++)
                wmma::load_matrix_sync(bf[j], &Kc[(wn + 16 * j) * ALD + 16 * ks], ALD);
            #pragma unroll
            for (int i = 0; i < 2; i++)
                #pragma unroll
                for (int j = 0; j < 2; j++)
                    wmma::mma_sync(sc[i][j], af[i], bf[j], sc[i][j]);
        }
        #pragma unroll
        for (int i = 0; i < 2; i++)
            #pragma unroll
            for (int j = 0; j < 2; j++)
                wmma::store_matrix_sync(&Ssh[(wm + 16 * i) * SLD + wn + 16 * j],
                                        sc[i][j], SLD, wmma::mem_row_major);
        __syncthreads();

        // fast exp (unnormalized) + row sums; P as fp16
        {
            int r = tid >> 1, c0 = (tid & 1) * 32;
            float sum = 0.f;
            #pragma unroll
            for (int cc = 0; cc < 32; cc += 2) {
                float p0 = __expf(Ssh[r * SLD + c0 + cc]     * SCALE);
                float p1 = __expf(Ssh[r * SLD + c0 + cc + 1] * SCALE);
                sum += p0 + p1;
                __half2 pv;
                pv.x = __float2half(p0);
                pv.y = __float2half(p1);
                *(__half2*)&Ph_s[r * ALD + c0 + cc] = pv;
            }
            sum += __shfl_xor_sync(0xffffffffu, sum, 1);
            if ((tid & 1) == 0) Lsh[r] += sum;
        }
        __syncthreads();

        // ctx += P . V  (single fp16 MMA)
        #pragma unroll
        for (int ks = 0; ks < 4; ks++) {
            wmma::fragment<wmma::matrix_a, 16, 16, 16, __half, wmma::row_major> af[2];
            wmma::fragment<wmma::matrix_b, 16, 16, 16, __half, wmma::row_major> bf[2];
            #pragma unroll
            for (int i = 0; i < 2; i++)
                wmma::load_matrix_sync(af[i], &Ph_s[(wm + 16 * i) * ALD + 16 * ks], ALD);
            #pragma unroll
            for (int j = 0; j < 2; j++)
                wmma::load_matrix_sync(bf[j], &Vc[16 * ks * ALD + wn + 16 * j], ALD);
            #pragma unroll
            for (int i = 0; i < 2; i++)
                #pragma unroll
                for (int j = 0; j < 2; j++)
                    wmma::mma_sync(ctx[i][j], af[i], bf[j], ctx[i][j]);
        }
    }
    __syncthreads();
    #pragma unroll
    for (int i = 0; i < 2; i++)
        #pragma unroll
        for (int j = 0; j < 2; j++)
            wmma::store_matrix_sync(&Ssh[(wm + 16 * i) * SLD + wn + 16 * j],
                                    ctx[i][j], SLD, wmma::mem_row_major);
    __syncthreads();

    {
        int r = tid >> 1, c0 = (tid & 1) * 32;
        float linv = 1.f / Lsh[r];
        int s = q0 + r;
        float* dst = out + ((size_t)b * SEQ + s) * DIM + h * HD + c0;
        #pragma unroll
        for (int cc = 0; cc < 32; cc += 4) {
            float4 v;
            v.x = Ssh[r * SLD + c0 + cc]     * linv;
            v.y = Ssh[r * SLD + c0 + cc + 1] * linv;
            v.z = Ssh[r * SLD + c0 + cc + 2] * linv;
            v.w = Ssh[r * SLD + c0 + cc + 3] * linv;
            *(float4*)(dst + cc) = v;
        }
    }
}

// ---------------------------------------------------------------------------
extern "C" void kernel_launch(void* const* d_in, const int* in_sizes, int n_in,
                              void* d_out, int out_size) {
    const float* X  = (const float*)d_in[0];
    const float* Wq = (const float*)d_in[1];
    const float* bq = (const float*)d_in[2];
    const float* Wk = (const float*)d_in[3];
    const float* bk = (const float*)d_in[4];
    const float* Wv = (const float*)d_in[5];
    const float* bv = (const float*)d_in[6];
    float* out = (float*)d_out;

    rope_table_kernel<<<(SEQ * DH + 255) / 256, 256>>>();

    split_kernel<<<(MTOT * DIM / 2 + 255) / 256, 256>>>(X, 0, MTOT * DIM / 2);
    split_kernel<<<(DIM * DIM / 2 + 255) / 256, 256>>>(Wq, 1, DIM * DIM / 2);
    split_kernel<<<(DIM * DIM / 2 + 255) / 256, 256>>>(Wk, 2, DIM * DIM / 2);
    split_kernel<<<(DIM * DIM / 2 + 255) / 256, 256>>>(Wv, 3, DIM * DIM / 2);

    cudaFuncSetAttribute(gemm_fused, cudaFuncAttributeMaxDynamicSharedMemorySize, PROJ_SMEM);
    dim3 ggrid(DIM / 128, MTOT / 128, 3);
    gemm_fused<<<ggrid, 256, PROJ_SMEM>>>(bq, bk, bv);

    cudaFuncSetAttribute(attn_wmma, cudaFuncAttributeMaxDynamicSharedMemorySize, ATTN_SMEM);
    dim3 agrid(SEQ / TQ, BATCH * NH);
    attn_wmma<<<agrid, 256, ATTN_SMEM>>>(out);
}

// round 13
// speedup vs baseline: 1.3988x; 1.3988x over previous
#include <cuda_runtime.h>
#include <cuda_fp16.h>
#include <mma.h>
#include <math.h>
#include <stdint.h>

using namespace nvcuda;

#define BATCH 2
#define SEQ 2048
#define DIM 1024
#define NH 16
#define HD 64
#define DH 32
#define MTOT (BATCH*SEQ)   // 4096
#define SCALE 0.125f

// ---------------- device scratch (no allocation allowed) -------------------
__device__ float g_sin[SEQ*DH], g_cos[SEQ*DH];
__device__ __half g_Xh[MTOT*DIM];
__device__ __half g_Wh[3][DIM*DIM];
__device__ __half g_Qh[MTOT*DIM];
__device__ __half g_Kh[MTOT*DIM];
__device__ __half g_Vh[MTOT*DIM];

// ---------------- PTX helpers ----------------------------------------------
#define CP_ASYNC16(dst_u32, src_ptr) \
    asm volatile("cp.async.cg.shared.global [%0], [%1], 16;" \
                 :: "r"(dst_u32), "l"(src_ptr) : "memory")
#define CP_COMMIT() asm volatile("cp.async.commit_group;" ::: "memory")
#define CP_WAIT0()  asm volatile("cp.async.wait_group 0;" ::: "memory")

#define LDSM_X2(r0, r1, addr) \
    asm volatile("ldmatrix.sync.aligned.m8n8.x2.shared.b16 {%0,%1}, [%2];" \
                 : "=r"(r0), "=r"(r1) : "r"(addr))
#define LDSM_X2_T(r0, r1, addr) \
    asm volatile("ldmatrix.sync.aligned.m8n8.x2.trans.shared.b16 {%0,%1}, [%2];" \
                 : "=r"(r0), "=r"(r1) : "r"(addr))
#define LDSM_X4(r0, r1, r2, r3, addr) \
    asm volatile("ldmatrix.sync.aligned.m8n8.x4.shared.b16 {%0,%1,%2,%3}, [%4];" \
                 : "=r"(r0), "=r"(r1), "=r"(r2), "=r"(r3) : "r"(addr))
#define MMA16816(c0, c1, c2, c3, a0, a1, a2, a3, b0, b1) \
    asm volatile("mma.sync.aligned.m16n8k16.row.col.f32.f16.f16.f32 " \
                 "{%0,%1,%2,%3}, {%4,%5,%6,%7}, {%8,%9}, {%0,%1,%2,%3};" \
                 : "+f"(c0), "+f"(c1), "+f"(c2), "+f"(c3) \
                 : "r"(a0), "r"(a1), "r"(a2), "r"(a3), "r"(b0), "r"(b1))

__device__ __forceinline__ uint32_t pack_h2(float a, float b) {
    __half2 t = __floats2half2_rn(a, b);   // .x = a (low 16), .y = b
    return *(uint32_t*)&t;
}

// ---------------------------------------------------------------------------
// RoPE tables in double precision (safe at large angles)
// ---------------------------------------------------------------------------
__global__ void rope_table_kernel() {
    int idx = blockIdx.x * blockDim.x + threadIdx.x;
    if (idx >= SEQ * DH) return;
    int s = idx / DH, i = idx % DH;
    double ang = (double)s * pow(10000.0, -((double)i) / (double)DH);
    g_sin[idx] = (float)sin(ang);
    g_cos[idx] = (float)cos(ang);
}

// ---------------------------------------------------------------------------
// Fused conversion: X and all three W -> fp16, one launch.
// ---------------------------------------------------------------------------
#define NX2 (MTOT*DIM/2)
#define NW2 (DIM*DIM/2)
__global__ void convert_all(const float* __restrict__ X,
                            const float* __restrict__ Wq,
                            const float* __restrict__ Wk,
                            const float* __restrict__ Wv) {
    int i = blockIdx.x * blockDim.x + threadIdx.x;
    const float* src;
    __half* dst;
    int off;
    if (i < NX2)               { src = X;  dst = g_Xh;    off = i; }
    else if (i < NX2 + NW2)    { src = Wq; dst = g_Wh[0]; off = i - NX2; }
    else if (i < NX2 + 2*NW2)  { src = Wk; dst = g_Wh[1]; off = i - NX2 - NW2; }
    else if (i < NX2 + 3*NW2)  { src = Wv; dst = g_Wh[2]; off = i - NX2 - 2*NW2; }
    else return;
    float2 x = ((const float2*)src)[off];
    __half2 hh;
    hh.x = __float2half(x.x);
    hh.y = __float2half(x.y);
    ((__half2*)dst)[off] = hh;
}

// ---------------------------------------------------------------------------
// Fused WMMA GEMM + epilogue (round-11 verified version: sync staging,
// 104KB smem -> 2 CTA/SM): Q/K/V = rope(X @ W^T + b) as fp16 [B,H,S,HD].
// ---------------------------------------------------------------------------
#define PLD 72
#define YLD 132
#define G_STAGE (2 * 128 * PLD * 2)  // 36864
#define PROJ_SMEM (G_STAGE + 128 * YLD * 4)   // 104448

__global__ __launch_bounds__(256) void gemm_fused(
    const float* __restrict__ bq, const float* __restrict__ bk,
    const float* __restrict__ bv)
{
    extern __shared__ __align__(128) char smraw[];
    __half* Ast = (__half*)smraw;
    __half* Bst = Ast + 128 * PLD;
    float*  Ysh = (float*)(smraw + G_STAGE);

    int tid = threadIdx.x, wid = tid >> 5;
    int n0 = blockIdx.x * 128, m0 = blockIdx.y * 128, which = blockIdx.z;

    const __half* Xp = g_Xh + (size_t)m0 * DIM;
    const __half* Wp = g_Wh[which] + (size_t)n0 * DIM;

    wmma::fragment<wmma::accumulator, 16, 16, 16, float> c[4][2];
    #pragma unroll
    for (int i = 0; i < 4; i++)
        #pragma unroll
        for (int j = 0; j < 2; j++) wmma::fill_fragment(c[i][j], 0.f);

    int wm = (wid >> 2) * 64, wn = (wid & 3) * 32;

    for (int k0 = 0; k0 < DIM; k0 += 64) {
        __syncthreads();
        #pragma unroll
        for (int i = 0; i < 4; i++) {
            int idx = tid + i * 256;
            int row = idx >> 3, c8 = (idx & 7) * 8;
            *(uint4*)&Ast[row * PLD + c8] = *(const uint4*)&Xp[row * DIM + k0 + c8];
            *(uint4*)&Bst[row * PLD + c8] = *(const uint4*)&Wp[row * DIM + k0 + c8];
        }
        __syncthreads();

        #pragma unroll
        for (int ks = 0; ks < 4; ks++) {
            wmma::fragment<wmma::matrix_a, 16, 16, 16, __half, wmma::row_major> af[4];
            wmma::fragment<wmma::matrix_b, 16, 16, 16, __half, wmma::col_major> bf[2];
            #pragma unroll
            for (int i = 0; i < 4; i++)
                wmma::load_matrix_sync(af[i], &Ast[(wm + 16 * i) * PLD + ks * 16], PLD);
            #pragma unroll
            for (int j = 0; j < 2; j++)
                wmma::load_matrix_sync(bf[j], &Bst[(wn + 16 * j) * PLD + ks * 16], PLD);
            #pragma unroll
            for (int i = 0; i < 4; i++)
                #pragma unroll
                for (int j = 0; j < 2; j++)
                    wmma::mma_sync(c[i][j], af[i], bf[j], c[i][j]);
        }
    }

    __syncthreads();
    #pragma unroll
    for (int i = 0; i < 4; i++)
        #pragma unroll
        for (int j = 0; j < 2; j++)
            wmma::store_matrix_sync(&Ysh[(wm + 16 * i) * YLD + wn + 16 * j],
                                    c[i][j], YLD, wmma::mem_row_major);
    __syncthreads();

    const float* bias = (which == 0) ? bq : (which == 1) ? bk : bv;
    __half* dstp = (which == 0) ? g_Qh : (which == 1) ? g_Kh : g_Vh;
    #pragma unroll
    for (int it = 0; it < 8; it++) {
        int idx = tid + it * 256;
        int q = idx & 7;
        int hh = (idx >> 3) & 1;
        int row = idx >> 4;
        int c0 = q * 4;
        int m = m0 + row, b = m / SEQ, s = m % SEQ;
        int h = (n0 >> 6) + hh;

        float o1[4], o2[4];
        #pragma unroll
        for (int t = 0; t < 4; t++) {
            o1[t] = Ysh[row * YLD + hh * 64 + c0 + t]      + bias[hh * 64 + n0 + c0 + t];
            o2[t] = Ysh[row * YLD + hh * 64 + c0 + DH + t] + bias[hh * 64 + n0 + c0 + DH + t];
        }
        if (which != 2) {
            #pragma unroll
            for (int t = 0; t < 4; t++) {
                float sn = g_sin[s * DH + c0 + t], cs = g_cos[s * DH + c0 + t];
                float a = o1[t], bb = o2[t];
                o1[t] = a * cs - bb * sn;
                o2[t] = a * sn + bb * cs;
            }
        }
        size_t base = ((size_t)(b * NH + h) * SEQ + s) * HD;
        #pragma unroll
        for (int half_i = 0; half_i < 2; half_i++) {
            float* o = half_i ? o2 : o1;
            size_t off = base + c0 + half_i * DH;
            __half2 v0, v1;
            v0.x = __float2half(o[0]); v0.y = __float2half(o[1]);
            v1.x = __float2half(o[2]); v1.y = __float2half(o[3]);
            *(__half2*)(dstp + off)     = v0;
            *(__half2*)(dstp + off + 2) = v1;
        }
    }
}

// ---------------------------------------------------------------------------
// Register-resident flash attention via raw mma.sync.m16n8k16 + ldmatrix.
// 128q x 64k tiles, 8 warps; each warp owns 16 q rows x ALL 64 keys.
// S, exp, P, row-sums all in registers; no softmax smem round-trip.
// cp.async double-buffered K/V; 1 sync per k-tile.
// ---------------------------------------------------------------------------
#define TQ 128
#define NT (SEQ / 64)
#define ALD 72
#define OFF_Q  0
#define OFF_K0 (OFF_Q + TQ*ALD*2)          // 18432
#define OFF_K1 (OFF_K0 + 64*ALD*2)         // 27648
#define OFF_V0 (OFF_K1 + 64*ALD*2)         // 36864
#define OFF_V1 (OFF_V0 + 64*ALD*2)         // 46080
#define ATTN_SMEM (OFF_V1 + 64*ALD*2)      // 55296

__global__ __launch_bounds__(256) void attn_mma(float* __restrict__ out) {
    extern __shared__ __align__(128) char smraw[];
    __half* Qs = (__half*)(smraw + OFF_Q);

    int tid = threadIdx.x, lane = tid & 31, wid = tid >> 5;
    int q0 = blockIdx.x * TQ, bh = blockIdx.y;
    int b = bh >> 4, h = bh & 15;
    int wq0 = wid * 16;                 // warp's q-row block
    int g = lane >> 2, tid4 = lane & 3; // mma fragment coords

    const __half* Qp = g_Qh + ((size_t)bh * SEQ + q0) * HD;
    const __half* Kp = g_Kh + (size_t)bh * SEQ * HD;
    const __half* Vp = g_Vh + (size_t)bh * SEQ * HD;

    uint32_t sb = (uint32_t)__cvta_generic_to_shared(smraw);

    // load Q tile to smem
    #pragma unroll
    for (int i = 0; i < 4; i++) {
        int idx = tid + i * 256;
        int row = idx >> 3, c8 = (idx & 7) * 8;
        *(uint4*)&Qs[row * ALD + c8] = *(const uint4*)&Qp[row * HD + c8];
    }
    // prefetch tile 0 K/V
    {
        int row = tid >> 3, c8 = (tid & 7) * 8;
        #pragma unroll
        for (int hf = 0; hf < 2; hf++) {
            int r = row + hf * 32;
            size_t gg = (size_t)r * HD + c8;
            CP_ASYNC16(sb + OFF_K0 + (r * ALD + c8) * 2, &Kp[gg]);
            CP_ASYNC16(sb + OFF_V0 + (r * ALD + c8) * 2, &Vp[gg]);
        }
        CP_COMMIT();
    }
    __syncthreads();

    // Q A-fragments: 4 k-chunks, ldmatrix.x4 per chunk
    uint32_t qa[4][4];
    {
        int quad = lane >> 3;
        int qrow = (lane & 7) + 8 * (quad & 1);
        int qcol = 8 * (quad >> 1);
        #pragma unroll
        for (int kc = 0; kc < 4; kc++) {
            uint32_t addr = sb + OFF_Q + ((wq0 + qrow) * ALD + kc * 16 + qcol) * 2;
            LDSM_X4(qa[kc][0], qa[kc][1], qa[kc][2], qa[kc][3], addr);
        }
    }

    float ctx[8][4];
    #pragma unroll
    for (int j = 0; j < 8; j++)
        #pragma unroll
        for (int t = 0; t < 4; t++) ctx[j][t] = 0.f;
    float rs0 = 0.f, rs1 = 0.f;

    int lrow = lane & 7, lsel = (lane >> 3) & 1;

    for (int kt = 0; kt < NT; kt++) {
        int cur = kt & 1;
        uint32_t Kc = sb + (cur ? OFF_K1 : OFF_K0);
        uint32_t Vc = sb + (cur ? OFF_V1 : OFF_V0);

        CP_WAIT0();
        __syncthreads();   // tile[cur] ready; tile[1-cur] reads finished last iter

        if (kt + 1 < NT) {
            uint32_t kb = sb + ((1 - cur) ? OFF_K1 : OFF_K0);
            uint32_t vb = sb + ((1 - cur) ? OFF_V1 : OFF_V0);
            int row = tid >> 3, c8 = (tid & 7) * 8;
            #pragma unroll
            for (int hf = 0; hf < 2; hf++) {
                int r = row + hf * 32;
                size_t gg = (size_t)((kt + 1) * 64 + r) * HD + c8;
                CP_ASYNC16(kb + (r * ALD + c8) * 2, &Kp[gg]);
                CP_ASYNC16(vb + (r * ALD + c8) * 2, &Vp[gg]);
            }
            CP_COMMIT();
        }

        // S tiles (8 x m16n8), exp in-register, pack P A-frags
        uint32_t pa[8][2];
        #pragma unroll
        for (int j = 0; j < 8; j++) {
            float c0 = 0.f, c1 = 0.f, c2 = 0.f, c3 = 0.f;
            #pragma unroll
            for (int kc = 0; kc < 4; kc++) {
                uint32_t b0, b1;
                uint32_t addr = Kc + ((j * 8 + lrow) * ALD + kc * 16 + 8 * lsel) * 2;
                LDSM_X2(b0, b1, addr);
                MMA16816(c0, c1, c2, c3,
                         qa[kc][0], qa[kc][1], qa[kc][2], qa[kc][3], b0, b1);
            }
            float p0 = __expf(c0 * SCALE);
            float p1 = __expf(c1 * SCALE);
            float p2 = __expf(c2 * SCALE);
            float p3 = __expf(c3 * SCALE);
            rs0 += p0 + p1;
            rs1 += p2 + p3;
            pa[j][0] = pack_h2(p0, p1);   // rows g   (A regs a0/a2 source)
            pa[j][1] = pack_h2(p2, p3);   // rows g+8 (A regs a1/a3 source)
        }

        // ctx += P . V  (B frags via ldmatrix.trans — no V transpose staging)
        #pragma unroll
        for (int j2 = 0; j2 < 8; j2++) {
            #pragma unroll
            for (int kc2 = 0; kc2 < 4; kc2++) {
                uint32_t b0, b1;
                uint32_t addr = Vc + ((kc2 * 16 + lrow + 8 * lsel) * ALD + j2 * 8) * 2;
                LDSM_X2_T(b0, b1, addr);
                MMA16816(ctx[j2][0], ctx[j2][1], ctx[j2][2], ctx[j2][3],
                         pa[2 * kc2][0], pa[2 * kc2][1],
                         pa[2 * kc2 + 1][0], pa[2 * kc2 + 1][1], b0, b1);
            }
        }
    }

    // row-sum butterfly over the 4 lanes sharing a row (bits 0-1 of lane)
    rs0 += __shfl_xor_sync(0xffffffffu, rs0, 1);
    rs0 += __shfl_xor_sync(0xffffffffu, rs0, 2);
    rs1 += __shfl_xor_sync(0xffffffffu, rs1, 1);
    rs1 += __shfl_xor_sync(0xffffffffu, rs1, 2);
    float inv0 = 1.f / rs0, inv1 = 1.f / rs1;

    int s0 = q0 + wq0 + g, s1 = s0 + 8;
    float* o0 = out + ((size_t)b * SEQ + s0) * DIM + h * HD + 2 * tid4;
    float* o1 = out + ((size_t)b * SEQ + s1) * DIM + h * HD + 2 * tid4;
    #pragma unroll
    for (int j2 = 0; j2 < 8; j2++) {
        float2 v0 = make_float2(ctx[j2][0] * inv0, ctx[j2][1] * inv0);
        float2 v1 = make_float2(ctx[j2][2] * inv1, ctx[j2][3] * inv1);
        *(float2*)(o0 + j2 * 8) = v0;
        *(float2*)(o1 + j2 * 8) = v1;
    }
}

// ---------------------------------------------------------------------------
extern "C" void kernel_launch(void* const* d_in, const int* in_sizes, int n_in,
                              void* d_out, int out_size) {
    const float* X  = (const float*)d_in[0];
    const float* Wq = (const float*)d_in[1];
    const float* bq = (const float*)d_in[2];
    const float* Wk = (const float*)d_in[3];
    const float* bk = (const float*)d_in[4];
    const float* Wv = (const float*)d_in[5];
    const float* bv = (const float*)d_in[6];
    float* out = (float*)d_out;

    rope_table_kernel<<<(SEQ * DH + 255) / 256, 256>>>();

    int ntot = NX2 + 3 * NW2;
    convert_all<<<(ntot + 255) / 256, 256>>>(X, Wq, Wk, Wv);

    cudaFuncSetAttribute(gemm_fused, cudaFuncAttributeMaxDynamicSharedMemorySize, PROJ_SMEM);
    dim3 ggrid(DIM / 128, MTOT / 128, 3);
    gemm_fused<<<ggrid, 256, PROJ_SMEM>>>(bq, bk, bv);

    cudaFuncSetAttribute(attn_mma, cudaFuncAttributeMaxDynamicSharedMemorySize, ATTN_SMEM);
    dim3 agrid(SEQ / TQ, BATCH * NH);
    attn_mma<<<agrid, 256, ATTN_SMEM>>>(out);
}

// round 14
// speedup vs baseline: 1.5042x; 1.0754x over previous
#include <cuda_runtime.h>
#include <cuda_fp16.h>
#include <math.h>
#include <stdint.h>

#define BATCH 2
#define SEQ 2048
#define DIM 1024
#define NH 16
#define HD 64
#define DH 32
#define MTOT (BATCH*SEQ)   // 4096
#define SCALE 0.125f

// ---------------- device scratch (no allocation allowed) -------------------
__device__ float g_sin[SEQ*DH], g_cos[SEQ*DH];
__device__ __half g_Xh[MTOT*DIM];
__device__ __half g_Wh[3][DIM*DIM];
__device__ __half g_Qh[MTOT*DIM];
__device__ __half g_Kh[MTOT*DIM];
__device__ __half g_Vh[MTOT*DIM];

// ---------------- PTX helpers ----------------------------------------------
#define CP_ASYNC16(dst_u32, src_ptr) \
    asm volatile("cp.async.cg.shared.global [%0], [%1], 16;" \
                 :: "r"(dst_u32), "l"(src_ptr) : "memory")
#define CP_COMMIT() asm volatile("cp.async.commit_group;" ::: "memory")
#define CP_WAIT0()  asm volatile("cp.async.wait_group 0;" ::: "memory")

#define LDSM_X4(r0, r1, r2, r3, addr) \
    asm volatile("ldmatrix.sync.aligned.m8n8.x4.shared.b16 {%0,%1,%2,%3}, [%4];" \
                 : "=r"(r0), "=r"(r1), "=r"(r2), "=r"(r3) : "r"(addr))
#define LDSM_X4_T(r0, r1, r2, r3, addr) \
    asm volatile("ldmatrix.sync.aligned.m8n8.x4.trans.shared.b16 {%0,%1,%2,%3}, [%4];" \
                 : "=r"(r0), "=r"(r1), "=r"(r2), "=r"(r3) : "r"(addr))
#define MMA16816(c0, c1, c2, c3, a0, a1, a2, a3, b0, b1) \
    asm volatile("mma.sync.aligned.m16n8k16.row.col.f32.f16.f16.f32 " \
                 "{%0,%1,%2,%3}, {%4,%5,%6,%7}, {%8,%9}, {%0,%1,%2,%3};" \
                 : "+f"(c0), "+f"(c1), "+f"(c2), "+f"(c3) \
                 : "r"(a0), "r"(a1), "r"(a2), "r"(a3), "r"(b0), "r"(b1))

__device__ __forceinline__ uint32_t pack_h2(float a, float b) {
    __half2 t = __floats2half2_rn(a, b);
    return *(uint32_t*)&t;
}

// ---------------------------------------------------------------------------
// RoPE tables in double precision
// ---------------------------------------------------------------------------
__global__ void rope_table_kernel() {
    int idx = blockIdx.x * blockDim.x + threadIdx.x;
    if (idx >= SEQ * DH) return;
    int s = idx / DH, i = idx % DH;
    double ang = (double)s * pow(10000.0, -((double)i) / (double)DH);
    g_sin[idx] = (float)sin(ang);
    g_cos[idx] = (float)cos(ang);
}

// ---------------------------------------------------------------------------
// Fused conversion: X and all three W -> fp16, one launch.
// ---------------------------------------------------------------------------
#define NX2 (MTOT*DIM/2)
#define NW2 (DIM*DIM/2)
__global__ void convert_all(const float* __restrict__ X,
                            const float* __restrict__ Wq,
                            const float* __restrict__ Wk,
                            const float* __restrict__ Wv) {
    int i = blockIdx.x * blockDim.x + threadIdx.x;
    const float* src;
    __half* dst;
    int off;
    if (i < NX2)               { src = X;  dst = g_Xh;    off = i; }
    else if (i < NX2 + NW2)    { src = Wq; dst = g_Wh[0]; off = i - NX2; }
    else if (i < NX2 + 2*NW2)  { src = Wk; dst = g_Wh[1]; off = i - NX2 - NW2; }
    else if (i < NX2 + 3*NW2)  { src = Wv; dst = g_Wh[2]; off = i - NX2 - 2*NW2; }
    else return;
    float2 x = ((const float2*)src)[off];
    __half2 hh;
    hh.x = __float2half(x.x);
    hh.y = __float2half(x.y);
    ((__half2*)dst)[off] = hh;
}

// ---------------------------------------------------------------------------
// Raw mma.sync GEMM + IN-REGISTER epilogue.
// Tile 128m x 128n, 8 warps (4m x 2n): warp = m32 x n64.
// k-chunk 64, cp.async double-buffered (73.7KB smem).
// Accumulator fragment coords are documented -> bias+RoPE+transpose+fp16
// store directly from registers (no Ysh, no epilogue barriers).
// ---------------------------------------------------------------------------
#define PLD 72
#define STG_MAT (128 * PLD * 2)       // 18432 per matrix
#define STG_B   (2 * STG_MAT)         // 36864 per stage (A+B)
#define PROJ_SMEM (2 * STG_B)         // 73728

__global__ __launch_bounds__(256) void gemm_mma(
    const float* __restrict__ bq, const float* __restrict__ bk,
    const float* __restrict__ bv)
{
    extern __shared__ __align__(128) char smraw[];
    int tid = threadIdx.x, lane = tid & 31, wid = tid >> 5;
    int n0 = blockIdx.x * 128, m0 = blockIdx.y * 128, which = blockIdx.z;
    int wmm = (wid >> 1) * 32, wnn = (wid & 1) * 64;
    int g = lane >> 2, tid4 = lane & 3;
    int quad = lane >> 3, qr = lane & 7;
    int aqrow = qr + 8 * (quad & 1), aqcol = 8 * (quad >> 1);

    const __half* Xp = g_Xh + (size_t)m0 * DIM;
    const __half* Wp = g_Wh[which] + (size_t)n0 * DIM;
    uint32_t sb = (uint32_t)__cvta_generic_to_shared(smraw);

    // prefetch k-chunk 0 -> stage 0
    #pragma unroll
    for (int i = 0; i < 4; i++) {
        int idx = tid + i * 256;
        int row = idx >> 3, c8 = (idx & 7) * 8;
        CP_ASYNC16(sb + (row * PLD + c8) * 2,           &Xp[row * DIM + c8]);
        CP_ASYNC16(sb + STG_MAT + (row * PLD + c8) * 2, &Wp[row * DIM + c8]);
    }
    CP_COMMIT();

    float acc[2][8][4];
    #pragma unroll
    for (int i = 0; i < 2; i++)
        #pragma unroll
        for (int j = 0; j < 8; j++)
            #pragma unroll
            for (int t = 0; t < 4; t++) acc[i][j][t] = 0.f;

    for (int it = 0; it < DIM / 64; it++) {
        int cur = it & 1;
        uint32_t Ast = sb + cur * STG_B;
        uint32_t Bst = Ast + STG_MAT;

        CP_WAIT0();
        __syncthreads();

        if (it + 1 < DIM / 64) {
            int k0n = (it + 1) * 64;
            uint32_t nb = sb + (1 - cur) * STG_B;
            #pragma unroll
            for (int i = 0; i < 4; i++) {
                int idx = tid + i * 256;
                int row = idx >> 3, c8 = (idx & 7) * 8;
                CP_ASYNC16(nb + (row * PLD + c8) * 2,           &Xp[row * DIM + k0n + c8]);
                CP_ASYNC16(nb + STG_MAT + (row * PLD + c8) * 2, &Wp[row * DIM + k0n + c8]);
            }
            CP_COMMIT();
        }

        // A fragments for this chunk: 2 m-tiles x 4 k-sub
        uint32_t qa[2][4][4];
        #pragma unroll
        for (int i = 0; i < 2; i++)
            #pragma unroll
            for (int kc = 0; kc < 4; kc++) {
                uint32_t addr = Ast + ((wmm + i * 16 + aqrow) * PLD + kc * 16 + aqcol) * 2;
                LDSM_X4(qa[i][kc][0], qa[i][kc][1], qa[i][kc][2], qa[i][kc][3], addr);
            }

        // B fragments (two n-tiles per x4) + MMAs
        #pragma unroll
        for (int jp = 0; jp < 4; jp++) {
            #pragma unroll
            for (int kc = 0; kc < 4; kc++) {
                uint32_t b0, b1, b2, b3;
                uint32_t addr = Bst + ((wnn + (2 * jp + (quad >> 1)) * 8 + qr) * PLD
                                       + kc * 16 + 8 * (quad & 1)) * 2;
                LDSM_X4(b0, b1, b2, b3, addr);
                #pragma unroll
                for (int i = 0; i < 2; i++) {
                    MMA16816(acc[i][2*jp][0], acc[i][2*jp][1], acc[i][2*jp][2], acc[i][2*jp][3],
                             qa[i][kc][0], qa[i][kc][1], qa[i][kc][2], qa[i][kc][3], b0, b1);
                    MMA16816(acc[i][2*jp+1][0], acc[i][2*jp+1][1], acc[i][2*jp+1][2], acc[i][2*jp+1][3],
                             qa[i][kc][0], qa[i][kc][1], qa[i][kc][2], qa[i][kc][3], b2, b3);
                }
            }
        }
    }

    // In-register epilogue: rows wmm+i*16+{g,g+8}; cols wnn + j*8 + 2*tid4 + e.
    // RoPE pair (c, c+32) lives in (acc[i][j], acc[i][j+4]) for j<4.
    const float* bias = (which == 0) ? bq : (which == 1) ? bk : bv;
    __half* dstp = (which == 0) ? g_Qh : (which == 1) ? g_Kh : g_Vh;
    int h = (n0 + wnn) >> 6;

    #pragma unroll
    for (int i = 0; i < 2; i++) {
        #pragma unroll
        for (int rh = 0; rh < 2; rh++) {
            int m = m0 + wmm + i * 16 + g + rh * 8;
            int bb = m / SEQ, s = m % SEQ;
            size_t base = ((size_t)(bb * NH + h) * SEQ + s) * HD;
            #pragma unroll
            for (int j = 0; j < 4; j++) {
                int c0 = j * 8 + 2 * tid4;   // within-head col of first-half pair
                float y1[2], y2[2];
                #pragma unroll
                for (int e = 0; e < 2; e++) {
                    y1[e] = acc[i][j][rh * 2 + e]     + bias[n0 + wnn + c0 + e];
                    y2[e] = acc[i][j + 4][rh * 2 + e] + bias[n0 + wnn + c0 + 32 + e];
                }
                float o1[2], o2[2];
                if (which != 2) {
                    #pragma unroll
                    for (int e = 0; e < 2; e++) {
                        float sn = g_sin[s * DH + c0 + e], cs = g_cos[s * DH + c0 + e];
                        o1[e] = y1[e] * cs - y2[e] * sn;
                        o2[e] = y1[e] * sn + y2[e] * cs;
                    }
                } else {
                    o1[0] = y1[0]; o1[1] = y1[1];
                    o2[0] = y2[0]; o2[1] = y2[1];
                }
                __half2 v1, v2;
                v1.x = __float2half(o1[0]); v1.y = __float2half(o1[1]);
                v2.x = __float2half(o2[0]); v2.y = __float2half(o2[1]);
                *(__half2*)(dstp + base + c0)      = v1;
                *(__half2*)(dstp + base + c0 + 32) = v2;
            }
        }
    }
}

// ---------------------------------------------------------------------------
// Register-resident flash attention (mma.sync + ldmatrix.x4).
// 128q x 64k tiles, 8 warps; warp = 16 q-rows x all 64 keys.
// ---------------------------------------------------------------------------
#define TQ 128
#define NT (SEQ / 64)
#define ALD 72
#define OFF_Q  0
#define OFF_K0 (OFF_Q + TQ*ALD*2)          // 18432
#define OFF_K1 (OFF_K0 + 64*ALD*2)         // 27648
#define OFF_V0 (OFF_K1 + 64*ALD*2)         // 36864
#define OFF_V1 (OFF_V0 + 64*ALD*2)         // 46080
#define ATTN_SMEM (OFF_V1 + 64*ALD*2)      // 55296

__global__ __launch_bounds__(256) void attn_mma(float* __restrict__ out) {
    extern __shared__ __align__(128) char smraw[];
    __half* Qs = (__half*)(smraw + OFF_Q);

    int tid = threadIdx.x, lane = tid & 31, wid = tid >> 5;
    int q0 = blockIdx.x * TQ, bh = blockIdx.y;
    int b = bh >> 4, h = bh & 15;
    int wq0 = wid * 16;
    int g = lane >> 2, tid4 = lane & 3;
    int quad = lane >> 3, qr = lane & 7;

    const __half* Qp = g_Qh + ((size_t)bh * SEQ + q0) * HD;
    const __half* Kp = g_Kh + (size_t)bh * SEQ * HD;
    const __half* Vp = g_Vh + (size_t)bh * SEQ * HD;

    uint32_t sb = (uint32_t)__cvta_generic_to_shared(smraw);

    #pragma unroll
    for (int i = 0; i < 4; i++) {
        int idx = tid + i * 256;
        int row = idx >> 3, c8 = (idx & 7) * 8;
        *(uint4*)&Qs[row * ALD + c8] = *(const uint4*)&Qp[row * HD + c8];
    }
    {
        int row = tid >> 3, c8 = (tid & 7) * 8;
        #pragma unroll
        for (int hf = 0; hf < 2; hf++) {
            int r = row + hf * 32;
            size_t gg = (size_t)r * HD + c8;
            CP_ASYNC16(sb + OFF_K0 + (r * ALD + c8) * 2, &Kp[gg]);
            CP_ASYNC16(sb + OFF_V0 + (r * ALD + c8) * 2, &Vp[gg]);
        }
        CP_COMMIT();
    }
    __syncthreads();

    // Q A-fragments
    uint32_t qa[4][4];
    {
        int aqrow = qr + 8 * (quad & 1), aqcol = 8 * (quad >> 1);
        #pragma unroll
        for (int kc = 0; kc < 4; kc++) {
            uint32_t addr = sb + OFF_Q + ((wq0 + aqrow) * ALD + kc * 16 + aqcol) * 2;
            LDSM_X4(qa[kc][0], qa[kc][1], qa[kc][2], qa[kc][3], addr);
        }
    }

    float ctx[8][4];
    #pragma unroll
    for (int j = 0; j < 8; j++)
        #pragma unroll
        for (int t = 0; t < 4; t++) ctx[j][t] = 0.f;
    float rs0 = 0.f, rs1 = 0.f;

    for (int kt = 0; kt < NT; kt++) {
        int cur = kt & 1;
        uint32_t Kc = sb + (cur ? OFF_K1 : OFF_K0);
        uint32_t Vc = sb + (cur ? OFF_V1 : OFF_V0);

        CP_WAIT0();
        __syncthreads();

        if (kt + 1 < NT) {
            uint32_t kb = sb + ((1 - cur) ? OFF_K1 : OFF_K0);
            uint32_t vb = sb + ((1 - cur) ? OFF_V1 : OFF_V0);
            int row = tid >> 3, c8 = (tid & 7) * 8;
            #pragma unroll
            for (int hf = 0; hf < 2; hf++) {
                int r = row + hf * 32;
                size_t gg = (size_t)((kt + 1) * 64 + r) * HD + c8;
                CP_ASYNC16(kb + (r * ALD + c8) * 2, &Kp[gg]);
                CP_ASYNC16(vb + (r * ALD + c8) * 2, &Vp[gg]);
            }
            CP_COMMIT();
        }

        // S tiles: two n-tiles per ldmatrix.x4
        uint32_t pa[8][2];
        #pragma unroll
        for (int jp = 0; jp < 4; jp++) {
            float ca[2][4];
            #pragma unroll
            for (int t2 = 0; t2 < 2; t2++)
                #pragma unroll
                for (int t = 0; t < 4; t++) ca[t2][t] = 0.f;
            #pragma unroll
            for (int kc = 0; kc < 4; kc++) {
                uint32_t b0, b1, b2, b3;
                uint32_t addr = Kc + (((2 * jp + (quad >> 1)) * 8 + qr) * ALD
                                      + kc * 16 + 8 * (quad & 1)) * 2;
                LDSM_X4(b0, b1, b2, b3, addr);
                MMA16816(ca[0][0], ca[0][1], ca[0][2], ca[0][3],
                         qa[kc][0], qa[kc][1], qa[kc][2], qa[kc][3], b0, b1);
                MMA16816(ca[1][0], ca[1][1], ca[1][2], ca[1][3],
                         qa[kc][0], qa[kc][1], qa[kc][2], qa[kc][3], b2, b3);
            }
            #pragma unroll
            for (int t2 = 0; t2 < 2; t2++) {
                int j = 2 * jp + t2;
                float p0 = __expf(ca[t2][0] * SCALE);
                float p1 = __expf(ca[t2][1] * SCALE);
                float p2 = __expf(ca[t2][2] * SCALE);
                float p3 = __expf(ca[t2][3] * SCALE);
                rs0 += p0 + p1;
                rs1 += p2 + p3;
                pa[j][0] = pack_h2(p0, p1);
                pa[j][1] = pack_h2(p2, p3);
            }
        }

        // ctx += P . V  (two n-tiles per ldmatrix.x4.trans)
        #pragma unroll
        for (int jp2 = 0; jp2 < 4; jp2++) {
            #pragma unroll
            for (int kc2 = 0; kc2 < 4; kc2++) {
                uint32_t b0, b1, b2, b3;
                uint32_t addr = Vc + ((kc2 * 16 + 8 * (quad & 1) + qr) * ALD
                                      + (2 * jp2 + (quad >> 1)) * 8) * 2;
                LDSM_X4_T(b0, b1, b2, b3, addr);
                MMA16816(ctx[2*jp2][0], ctx[2*jp2][1], ctx[2*jp2][2], ctx[2*jp2][3],
                         pa[2*kc2][0], pa[2*kc2][1], pa[2*kc2+1][0], pa[2*kc2+1][1], b0, b1);
                MMA16816(ctx[2*jp2+1][0], ctx[2*jp2+1][1], ctx[2*jp2+1][2], ctx[2*jp2+1][3],
                         pa[2*kc2][0], pa[2*kc2][1], pa[2*kc2+1][0], pa[2*kc2+1][1], b2, b3);
            }
        }
    }

    rs0 += __shfl_xor_sync(0xffffffffu, rs0, 1);
    rs0 += __shfl_xor_sync(0xffffffffu, rs0, 2);
    rs1 += __shfl_xor_sync(0xffffffffu, rs1, 1);
    rs1 += __shfl_xor_sync(0xffffffffu, rs1, 2);
    float inv0 = 1.f / rs0, inv1 = 1.f / rs1;

    int s0 = q0 + wq0 + g, s1 = s0 + 8;
    float* o0 = out + ((size_t)b * SEQ + s0) * DIM + h * HD + 2 * tid4;
    float* o1 = out + ((size_t)b * SEQ + s1) * DIM + h * HD + 2 * tid4;
    #pragma unroll
    for (int j2 = 0; j2 < 8; j2++) {
        float2 v0 = make_float2(ctx[j2][0] * inv0, ctx[j2][1] * inv0);
        float2 v1 = make_float2(ctx[j2][2] * inv1, ctx[j2][3] * inv1);
        *(float2*)(o0 + j2 * 8) = v0;
        *(float2*)(o1 + j2 * 8) = v1;
    }
}

// ---------------------------------------------------------------------------
extern "C" void kernel_launch(void* const* d_in, const int* in_sizes, int n_in,
                              void* d_out, int out_size) {
    const float* X  = (const float*)d_in[0];
    const float* Wq = (const float*)d_in[1];
    const float* bq = (const float*)d_in[2];
    const float* Wk = (const float*)d_in[3];
    const float* bk = (const float*)d_in[4];
    const float* Wv = (const float*)d_in[5];
    const float* bv = (const float*)d_in[6];
    float* out = (float*)d_out;

    rope_table_kernel<<<(SEQ * DH + 255) / 256, 256>>>();

    int ntot = NX2 + 3 * NW2;
    convert_all<<<(ntot + 255) / 256, 256>>>(X, Wq, Wk, Wv);

    cudaFuncSetAttribute(gemm_mma, cudaFuncAttributeMaxDynamicSharedMemorySize, PROJ_SMEM);
    dim3 ggrid(DIM / 128, MTOT / 128, 3);
    gemm_mma<<<ggrid, 256, PROJ_SMEM>>>(bq, bk, bv);

    cudaFuncSetAttribute(attn_mma, cudaFuncAttributeMaxDynamicSharedMemorySize, ATTN_SMEM);
    dim3 agrid(SEQ / TQ, BATCH * NH);
    attn_mma<<<agrid, 256, ATTN_SMEM>>>(out);
}

// round 15
// speedup vs baseline: 1.5052x; 1.0007x over previous
#include <cuda_runtime.h>
#include <cuda_fp16.h>
#include <math.h>
#include <stdint.h>

#define BATCH 2
#define SEQ 2048
#define DIM 1024
#define NH 16
#define HD 64
#define DH 32
#define MTOT (BATCH*SEQ)   // 4096
#define SCALE 0.125f

// ---------------- device scratch (no allocation allowed) -------------------
__device__ float g_sin[SEQ*DH], g_cos[SEQ*DH];
__device__ __half g_Xh[MTOT*DIM];
__device__ __half g_Wh[3][DIM*DIM];
__device__ __half g_Qh[MTOT*DIM];
__device__ __half g_Kh[MTOT*DIM];
__device__ __half g_Vh[MTOT*DIM];

// ---------------- PTX helpers ----------------------------------------------
#define CP_ASYNC16(dst_u32, src_ptr) \
    asm volatile("cp.async.cg.shared.global [%0], [%1], 16;" \
                 :: "r"(dst_u32), "l"(src_ptr) : "memory")
#define CP_COMMIT() asm volatile("cp.async.commit_group;" ::: "memory")
#define CP_WAIT0()  asm volatile("cp.async.wait_group 0;" ::: "memory")

#define LDSM_X4(r0, r1, r2, r3, addr) \
    asm volatile("ldmatrix.sync.aligned.m8n8.x4.shared.b16 {%0,%1,%2,%3}, [%4];" \
                 : "=r"(r0), "=r"(r1), "=r"(r2), "=r"(r3) : "r"(addr))
#define LDSM_X4_T(r0, r1, r2, r3, addr) \
    asm volatile("ldmatrix.sync.aligned.m8n8.x4.trans.shared.b16 {%0,%1,%2,%3}, [%4];" \
                 : "=r"(r0), "=r"(r1), "=r"(r2), "=r"(r3) : "r"(addr))
#define MMA16816(c0, c1, c2, c3, a0, a1, a2, a3, b0, b1) \
    asm volatile("mma.sync.aligned.m16n8k16.row.col.f32.f16.f16.f32 " \
                 "{%0,%1,%2,%3}, {%4,%5,%6,%7}, {%8,%9}, {%0,%1,%2,%3};" \
                 : "+f"(c0), "+f"(c1), "+f"(c2), "+f"(c3) \
                 : "r"(a0), "r"(a1), "r"(a2), "r"(a3), "r"(b0), "r"(b1))

__device__ __forceinline__ uint32_t pack_h2(float a, float b) {
    __half2 t = __floats2half2_rn(a, b);
    return *(uint32_t*)&t;
}

// ---------------------------------------------------------------------------
// RoPE tables in double precision
// ---------------------------------------------------------------------------
__global__ void rope_table_kernel() {
    int idx = blockIdx.x * blockDim.x + threadIdx.x;
    if (idx >= SEQ * DH) return;
    int s = idx / DH, i = idx % DH;
    double ang = (double)s * pow(10000.0, -((double)i) / (double)DH);
    g_sin[idx] = (float)sin(ang);
    g_cos[idx] = (float)cos(ang);
}

// ---------------------------------------------------------------------------
// Fused conversion: X and all three W -> fp16, one launch.
// ---------------------------------------------------------------------------
#define NX2 (MTOT*DIM/2)
#define NW2 (DIM*DIM/2)
__global__ void convert_all(const float* __restrict__ X,
                            const float* __restrict__ Wq,
                            const float* __restrict__ Wk,
                            const float* __restrict__ Wv) {
    int i = blockIdx.x * blockDim.x + threadIdx.x;
    const float* src;
    __half* dst;
    int off;
    if (i < NX2)               { src = X;  dst = g_Xh;    off = i; }
    else if (i < NX2 + NW2)    { src = Wq; dst = g_Wh[0]; off = i - NX2; }
    else if (i < NX2 + 2*NW2)  { src = Wk; dst = g_Wh[1]; off = i - NX2 - NW2; }
    else if (i < NX2 + 3*NW2)  { src = Wv; dst = g_Wh[2]; off = i - NX2 - 2*NW2; }
    else return;
    float2 x = ((const float2*)src)[off];
    __half2 hh;
    hh.x = __float2half(x.x);
    hh.y = __float2half(x.y);
    ((__half2*)dst)[off] = hh;
}

// ---------------------------------------------------------------------------
// Raw mma.sync GEMM + IN-REGISTER epilogue (unchanged from round 14).
// ---------------------------------------------------------------------------
#define PLD 72
#define STG_MAT (128 * PLD * 2)       // 18432 per matrix
#define STG_B   (2 * STG_MAT)         // 36864 per stage (A+B)
#define PROJ_SMEM (2 * STG_B)         // 73728

__global__ __launch_bounds__(256) void gemm_mma(
    const float* __restrict__ bq, const float* __restrict__ bk,
    const float* __restrict__ bv)
{
    extern __shared__ __align__(128) char smraw[];
    int tid = threadIdx.x, lane = tid & 31, wid = tid >> 5;
    int n0 = blockIdx.x * 128, m0 = blockIdx.y * 128, which = blockIdx.z;
    int wmm = (wid >> 1) * 32, wnn = (wid & 1) * 64;
    int g = lane >> 2, tid4 = lane & 3;
    int quad = lane >> 3, qr = lane & 7;
    int aqrow = qr + 8 * (quad & 1), aqcol = 8 * (quad >> 1);

    const __half* Xp = g_Xh + (size_t)m0 * DIM;
    const __half* Wp = g_Wh[which] + (size_t)n0 * DIM;
    uint32_t sb = (uint32_t)__cvta_generic_to_shared(smraw);

    #pragma unroll
    for (int i = 0; i < 4; i++) {
        int idx = tid + i * 256;
        int row = idx >> 3, c8 = (idx & 7) * 8;
        CP_ASYNC16(sb + (row * PLD + c8) * 2,           &Xp[row * DIM + c8]);
        CP_ASYNC16(sb + STG_MAT + (row * PLD + c8) * 2, &Wp[row * DIM + c8]);
    }
    CP_COMMIT();

    float acc[2][8][4];
    #pragma unroll
    for (int i = 0; i < 2; i++)
        #pragma unroll
        for (int j = 0; j < 8; j++)
            #pragma unroll
            for (int t = 0; t < 4; t++) acc[i][j][t] = 0.f;

    for (int it = 0; it < DIM / 64; it++) {
        int cur = it & 1;
        uint32_t Ast = sb + cur * STG_B;
        uint32_t Bst = Ast + STG_MAT;

        CP_WAIT0();
        __syncthreads();

        if (it + 1 < DIM / 64) {
            int k0n = (it + 1) * 64;
            uint32_t nb = sb + (1 - cur) * STG_B;
            #pragma unroll
            for (int i = 0; i < 4; i++) {
                int idx = tid + i * 256;
                int row = idx >> 3, c8 = (idx & 7) * 8;
                CP_ASYNC16(nb + (row * PLD + c8) * 2,           &Xp[row * DIM + k0n + c8]);
                CP_ASYNC16(nb + STG_MAT + (row * PLD + c8) * 2, &Wp[row * DIM + k0n + c8]);
            }
            CP_COMMIT();
        }

        uint32_t qa[2][4][4];
        #pragma unroll
        for (int i = 0; i < 2; i++)
            #pragma unroll
            for (int kc = 0; kc < 4; kc++) {
                uint32_t addr = Ast + ((wmm + i * 16 + aqrow) * PLD + kc * 16 + aqcol) * 2;
                LDSM_X4(qa[i][kc][0], qa[i][kc][1], qa[i][kc][2], qa[i][kc][3], addr);
            }

        #pragma unroll
        for (int jp = 0; jp < 4; jp++) {
            #pragma unroll
            for (int kc = 0; kc < 4; kc++) {
                uint32_t b0, b1, b2, b3;
                uint32_t addr = Bst + ((wnn + (2 * jp + (quad >> 1)) * 8 + qr) * PLD
                                       + kc * 16 + 8 * (quad & 1)) * 2;
                LDSM_X4(b0, b1, b2, b3, addr);
                #pragma unroll
                for (int i = 0; i < 2; i++) {
                    MMA16816(acc[i][2*jp][0], acc[i][2*jp][1], acc[i][2*jp][2], acc[i][2*jp][3],
                             qa[i][kc][0], qa[i][kc][1], qa[i][kc][2], qa[i][kc][3], b0, b1);
                    MMA16816(acc[i][2*jp+1][0], acc[i][2*jp+1][1], acc[i][2*jp+1][2], acc[i][2*jp+1][3],
                             qa[i][kc][0], qa[i][kc][1], qa[i][kc][2], qa[i][kc][3], b2, b3);
                }
            }
        }
    }

    const float* bias = (which == 0) ? bq : (which == 1) ? bk : bv;
    __half* dstp = (which == 0) ? g_Qh : (which == 1) ? g_Kh : g_Vh;
    int h = (n0 + wnn) >> 6;

    #pragma unroll
    for (int i = 0; i < 2; i++) {
        #pragma unroll
        for (int rh = 0; rh < 2; rh++) {
            int m = m0 + wmm + i * 16 + g + rh * 8;
            int bb = m / SEQ, s = m % SEQ;
            size_t base = ((size_t)(bb * NH + h) * SEQ + s) * HD;
            #pragma unroll
            for (int j = 0; j < 4; j++) {
                int c0 = j * 8 + 2 * tid4;
                float y1[2], y2[2];
                #pragma unroll
                for (int e = 0; e < 2; e++) {
                    y1[e] = acc[i][j][rh * 2 + e]     + bias[n0 + wnn + c0 + e];
                    y2[e] = acc[i][j + 4][rh * 2 + e] + bias[n0 + wnn + c0 + 32 + e];
                }
                float o1[2], o2[2];
                if (which != 2) {
                    #pragma unroll
                    for (int e = 0; e < 2; e++) {
                        float sn = g_sin[s * DH + c0 + e], cs = g_cos[s * DH + c0 + e];
                        o1[e] = y1[e] * cs - y2[e] * sn;
                        o2[e] = y1[e] * sn + y2[e] * cs;
                    }
                } else {
                    o1[0] = y1[0]; o1[1] = y1[1];
                    o2[0] = y2[0]; o2[1] = y2[1];
                }
                __half2 v1, v2;
                v1.x = __float2half(o1[0]); v1.y = __float2half(o1[1]);
                v2.x = __float2half(o2[0]); v2.y = __float2half(o2[1]);
                *(__half2*)(dstp + base + c0)      = v1;
                *(__half2*)(dstp + base + c0 + 32) = v2;
            }
        }
    }
}

// ---------------------------------------------------------------------------
// Register-resident flash attention, 4 warps x 32 q-rows (2 m-tiles/warp):
// each K/V fragment feeds 4 MMAs (was 2) -> ldmatrix-per-MMA halved.
// 128 threads, TQ=128, cp.async double-buffered K/V.
// ---------------------------------------------------------------------------
#define TQ 128
#define NT (SEQ / 64)
#define ALD 72
#define OFF_Q  0
#define OFF_K0 (OFF_Q + TQ*ALD*2)          // 18432
#define OFF_K1 (OFF_K0 + 64*ALD*2)         // 27648
#define OFF_V0 (OFF_K1 + 64*ALD*2)         // 36864
#define OFF_V1 (OFF_V0 + 64*ALD*2)         // 46080
#define ATTN_SMEM (OFF_V1 + 64*ALD*2)      // 55296

__global__ __launch_bounds__(128) void attn_mma(float* __restrict__ out) {
    extern __shared__ __align__(128) char smraw[];
    __half* Qs = (__half*)(smraw + OFF_Q);

    int tid = threadIdx.x, lane = tid & 31, wid = tid >> 5;   // 4 warps
    int q0 = blockIdx.x * TQ, bh = blockIdx.y;
    int b = bh >> 4, h = bh & 15;
    int wq0 = wid * 32;                    // warp's 32-row q block
    int g = lane >> 2, tid4 = lane & 3;
    int quad = lane >> 3, qr = lane & 7;

    const __half* Qp = g_Qh + ((size_t)bh * SEQ + q0) * HD;
    const __half* Kp = g_Kh + (size_t)bh * SEQ * HD;
    const __half* Vp = g_Vh + (size_t)bh * SEQ * HD;

    uint32_t sb = (uint32_t)__cvta_generic_to_shared(smraw);

    // load Q tile (128 x 64 fp16): 1024 uint4 / 128 threads = 8 each
    #pragma unroll
    for (int i = 0; i < 8; i++) {
        int idx = tid + i * 128;
        int row = idx >> 3, c8 = (idx & 7) * 8;
        *(uint4*)&Qs[row * ALD + c8] = *(const uint4*)&Qp[row * HD + c8];
    }
    // prefetch tile 0 K/V (64 rows): 512 uint4 per matrix / 128 thr = 4 each
    {
        int row = tid >> 3, c8 = (tid & 7) * 8;   // row 0..15
        #pragma unroll
        for (int hf = 0; hf < 4; hf++) {
            int r = row + hf * 16;
            size_t gg = (size_t)r * HD + c8;
            CP_ASYNC16(sb + OFF_K0 + (r * ALD + c8) * 2, &Kp[gg]);
            CP_ASYNC16(sb + OFF_V0 + (r * ALD + c8) * 2, &Vp[gg]);
        }
        CP_COMMIT();
    }
    __syncthreads();

    // Q A-fragments: 2 m-tiles x 4 k-chunks
    uint32_t qa[2][4][4];
    {
        int aqrow = qr + 8 * (quad & 1), aqcol = 8 * (quad >> 1);
        #pragma unroll
        for (int i = 0; i < 2; i++)
            #pragma unroll
            for (int kc = 0; kc < 4; kc++) {
                uint32_t addr = sb + OFF_Q + ((wq0 + i * 16 + aqrow) * ALD + kc * 16 + aqcol) * 2;
                LDSM_X4(qa[i][kc][0], qa[i][kc][1], qa[i][kc][2], qa[i][kc][3], addr);
            }
    }

    float ctx[2][8][4];
    #pragma unroll
    for (int i = 0; i < 2; i++)
        #pragma unroll
        for (int j = 0; j < 8; j++)
            #pragma unroll
            for (int t = 0; t < 4; t++) ctx[i][j][t] = 0.f;
    float rs[2][2] = {{0.f, 0.f}, {0.f, 0.f}};

    for (int kt = 0; kt < NT; kt++) {
        int cur = kt & 1;
        uint32_t Kc = sb + (cur ? OFF_K1 : OFF_K0);
        uint32_t Vc = sb + (cur ? OFF_V1 : OFF_V0);

        CP_WAIT0();
        __syncthreads();

        if (kt + 1 < NT) {
            uint32_t kb = sb + ((1 - cur) ? OFF_K1 : OFF_K0);
            uint32_t vb = sb + ((1 - cur) ? OFF_V1 : OFF_V0);
            int row = tid >> 3, c8 = (tid & 7) * 8;
            #pragma unroll
            for (int hf = 0; hf < 4; hf++) {
                int r = row + hf * 16;
                size_t gg = (size_t)((kt + 1) * 64 + r) * HD + c8;
                CP_ASYNC16(kb + (r * ALD + c8) * 2, &Kp[gg]);
                CP_ASYNC16(vb + (r * ALD + c8) * 2, &Vp[gg]);
            }
            CP_COMMIT();
        }

        // S for BOTH m-tiles inside the kc loop (K frag reused 4x)
        uint32_t pa[2][8][2];
        #pragma unroll
        for (int jp = 0; jp < 4; jp++) {
            float ca[2][2][4];
            #pragma unroll
            for (int i = 0; i < 2; i++)
                #pragma unroll
                for (int t2 = 0; t2 < 2; t2++)
                    #pragma unroll
                    for (int t = 0; t < 4; t++) ca[i][t2][t] = 0.f;
            #pragma unroll
            for (int kc = 0; kc < 4; kc++) {
                uint32_t b0, b1, b2, b3;
                uint32_t addr = Kc + (((2 * jp + (quad >> 1)) * 8 + qr) * ALD
                                      + kc * 16 + 8 * (quad & 1)) * 2;
                LDSM_X4(b0, b1, b2, b3, addr);
                #pragma unroll
                for (int i = 0; i < 2; i++) {
                    MMA16816(ca[i][0][0], ca[i][0][1], ca[i][0][2], ca[i][0][3],
                             qa[i][kc][0], qa[i][kc][1], qa[i][kc][2], qa[i][kc][3], b0, b1);
                    MMA16816(ca[i][1][0], ca[i][1][1], ca[i][1][2], ca[i][1][3],
                             qa[i][kc][0], qa[i][kc][1], qa[i][kc][2], qa[i][kc][3], b2, b3);
                }
            }
            #pragma unroll
            for (int i = 0; i < 2; i++)
                #pragma unroll
                for (int t2 = 0; t2 < 2; t2++) {
                    int j = 2 * jp + t2;
                    float p0 = __expf(ca[i][t2][0] * SCALE);
                    float p1 = __expf(ca[i][t2][1] * SCALE);
                    float p2 = __expf(ca[i][t2][2] * SCALE);
                    float p3 = __expf(ca[i][t2][3] * SCALE);
                    rs[i][0] += p0 + p1;
                    rs[i][1] += p2 + p3;
                    pa[i][j][0] = pack_h2(p0, p1);
                    pa[i][j][1] = pack_h2(p2, p3);
                }
        }

        // ctx += P . V  (V frag reused 4x)
        #pragma unroll
        for (int jp2 = 0; jp2 < 4; jp2++) {
            #pragma unroll
            for (int kc2 = 0; kc2 < 4; kc2++) {
                uint32_t b0, b1, b2, b3;
                uint32_t addr = Vc + ((kc2 * 16 + 8 * (quad & 1) + qr) * ALD
                                      + (2 * jp2 + (quad >> 1)) * 8) * 2;
                LDSM_X4_T(b0, b1, b2, b3, addr);
                #pragma unroll
                for (int i = 0; i < 2; i++) {
                    MMA16816(ctx[i][2*jp2][0], ctx[i][2*jp2][1], ctx[i][2*jp2][2], ctx[i][2*jp2][3],
                             pa[i][2*kc2][0], pa[i][2*kc2][1],
                             pa[i][2*kc2+1][0], pa[i][2*kc2+1][1], b0, b1);
                    MMA16816(ctx[i][2*jp2+1][0], ctx[i][2*jp2+1][1], ctx[i][2*jp2+1][2], ctx[i][2*jp2+1][3],
                             pa[i][2*kc2][0], pa[i][2*kc2][1],
                             pa[i][2*kc2+1][0], pa[i][2*kc2+1][1], b2, b3);
                }
            }
        }
    }

    // row-sum butterflies + output
    #pragma unroll
    for (int i = 0; i < 2; i++) {
        rs[i][0] += __shfl_xor_sync(0xffffffffu, rs[i][0], 1);
        rs[i][0] += __shfl_xor_sync(0xffffffffu, rs[i][0], 2);
        rs[i][1] += __shfl_xor_sync(0xffffffffu, rs[i][1], 1);
        rs[i][1] += __shfl_xor_sync(0xffffffffu, rs[i][1], 2);
        float inv0 = 1.f / rs[i][0], inv1 = 1.f / rs[i][1];

        int s0 = q0 + wq0 + i * 16 + g, s1 = s0 + 8;
        float* o0 = out + ((size_t)b * SEQ + s0) * DIM + h * HD + 2 * tid4;
        float* o1 = out + ((size_t)b * SEQ + s1) * DIM + h * HD + 2 * tid4;
        #pragma unroll
        for (int j2 = 0; j2 < 8; j2++) {
            float2 v0 = make_float2(ctx[i][j2][0] * inv0, ctx[i][j2][1] * inv0);
            float2 v1 = make_float2(ctx[i][j2][2] * inv1, ctx[i][j2][3] * inv1);
            *(float2*)(o0 + j2 * 8) = v0;
            *(float2*)(o1 + j2 * 8) = v1;
        }
    }
}

// ---------------------------------------------------------------------------
extern "C" void kernel_launch(void* const* d_in, const int* in_sizes, int n_in,
                              void* d_out, int out_size) {
    const float* X  = (const float*)d_in[0];
    const float* Wq = (const float*)d_in[1];
    const float* bq = (const float*)d_in[2];
    const float* Wk = (const float*)d_in[3];
    const float* bk = (const float*)d_in[4];
    const float* Wv = (const float*)d_in[5];
    const float* bv = (const float*)d_in[6];
    float* out = (float*)d_out;

    rope_table_kernel<<<(SEQ * DH + 255) / 256, 256>>>();

    int ntot = NX2 + 3 * NW2;
    convert_all<<<(ntot + 255) / 256, 256>>>(X, Wq, Wk, Wv);

    cudaFuncSetAttribute(gemm_mma, cudaFuncAttributeMaxDynamicSharedMemorySize, PROJ_SMEM);
    dim3 ggrid(DIM / 128, MTOT / 128, 3);
    gemm_mma<<<ggrid, 256, PROJ_SMEM>>>(bq, bk, bv);

    cudaFuncSetAttribute(attn_mma, cudaFuncAttributeMaxDynamicSharedMemorySize, ATTN_SMEM);
    dim3 agrid(SEQ / TQ, BATCH * NH);
    attn_mma<<<agrid, 128, ATTN_SMEM>>>(out);
}

// round 16
// speedup vs baseline: 1.5960x; 1.0603x over previous
#include <cuda_runtime.h>
#include <cuda_fp16.h>
#include <math.h>
#include <stdint.h>

#define BATCH 2
#define SEQ 2048
#define DIM 1024
#define NH 16
#define HD 64
#define DH 32
#define MTOT (BATCH*SEQ)   // 4096
#define QSCALE 0.1803368801111204f   // (1/sqrt(64)) * log2(e)

// ---------------- device scratch (no allocation allowed) -------------------
__device__ float g_sin[SEQ*DH], g_cos[SEQ*DH];
__device__ __half g_Xh[MTOT*DIM];
__device__ __half g_Wh[3][DIM*DIM];
__device__ __half g_Qh[MTOT*DIM];
__device__ __half g_Kh[MTOT*DIM];
__device__ __half g_Vh[MTOT*DIM];

// ---------------- PTX helpers ----------------------------------------------
#define CP_ASYNC16(dst_u32, src_ptr) \
    asm volatile("cp.async.cg.shared.global [%0], [%1], 16;" \
                 :: "r"(dst_u32), "l"(src_ptr) : "memory")
#define CP_COMMIT() asm volatile("cp.async.commit_group;" ::: "memory")
#define CP_WAIT0()  asm volatile("cp.async.wait_group 0;" ::: "memory")

#define LDSM_X4(r0, r1, r2, r3, addr) \
    asm volatile("ldmatrix.sync.aligned.m8n8.x4.shared.b16 {%0,%1,%2,%3}, [%4];" \
                 : "=r"(r0), "=r"(r1), "=r"(r2), "=r"(r3) : "r"(addr))
#define LDSM_X4_T(r0, r1, r2, r3, addr) \
    asm volatile("ldmatrix.sync.aligned.m8n8.x4.trans.shared.b16 {%0,%1,%2,%3}, [%4];" \
                 : "=r"(r0), "=r"(r1), "=r"(r2), "=r"(r3) : "r"(addr))
#define MMA16816(c0, c1, c2, c3, a0, a1, a2, a3, b0, b1) \
    asm volatile("mma.sync.aligned.m16n8k16.row.col.f32.f16.f16.f32 " \
                 "{%0,%1,%2,%3}, {%4,%5,%6,%7}, {%8,%9}, {%0,%1,%2,%3};" \
                 : "+f"(c0), "+f"(c1), "+f"(c2), "+f"(c3) \
                 : "r"(a0), "r"(a1), "r"(a2), "r"(a3), "r"(b0), "r"(b1))
#define EX2_H2(dst, src) \
    asm("ex2.approx.f16x2 %0, %1;" : "=r"(dst) : "r"(src))

__device__ __forceinline__ uint32_t pack_h2(float a, float b) {
    __half2 t = __floats2half2_rn(a, b);
    return *(uint32_t*)&t;
}
__device__ __forceinline__ float2 h2_to_f2(uint32_t u) {
    return __half22float2(*(__half2*)&u);
}

// ---------------------------------------------------------------------------
// RoPE tables in double precision
// ---------------------------------------------------------------------------
__global__ void rope_table_kernel() {
    int idx = blockIdx.x * blockDim.x + threadIdx.x;
    if (idx >= SEQ * DH) return;
    int s = idx / DH, i = idx % DH;
    double ang = (double)s * pow(10000.0, -((double)i) / (double)DH);
    g_sin[idx] = (float)sin(ang);
    g_cos[idx] = (float)cos(ang);
}

// ---------------------------------------------------------------------------
// Fused conversion: X and all three W -> fp16, one launch.
// ---------------------------------------------------------------------------
#define NX2 (MTOT*DIM/2)
#define NW2 (DIM*DIM/2)
__global__ void convert_all(const float* __restrict__ X,
                            const float* __restrict__ Wq,
                            const float* __restrict__ Wk,
                            const float* __restrict__ Wv) {
    int i = blockIdx.x * blockDim.x + threadIdx.x;
    const float* src;
    __half* dst;
    int off;
    if (i < NX2)               { src = X;  dst = g_Xh;    off = i; }
    else if (i < NX2 + NW2)    { src = Wq; dst = g_Wh[0]; off = i - NX2; }
    else if (i < NX2 + 2*NW2)  { src = Wk; dst = g_Wh[1]; off = i - NX2 - NW2; }
    else if (i < NX2 + 3*NW2)  { src = Wv; dst = g_Wh[2]; off = i - NX2 - 2*NW2; }
    else return;
    float2 x = ((const float2*)src)[off];
    __half2 hh;
    hh.x = __float2half(x.x);
    hh.y = __float2half(x.y);
    ((__half2*)dst)[off] = hh;
}

// ---------------------------------------------------------------------------
// Raw mma.sync GEMM + IN-REGISTER epilogue.
// Q is pre-scaled by QSCALE so attention scores land in the exp2 domain.
// ---------------------------------------------------------------------------
#define PLD 72
#define STG_MAT (128 * PLD * 2)       // 18432 per matrix
#define STG_B   (2 * STG_MAT)         // 36864 per stage (A+B)
#define PROJ_SMEM (2 * STG_B)         // 73728

__global__ __launch_bounds__(256) void gemm_mma(
    const float* __restrict__ bq, const float* __restrict__ bk,
    const float* __restrict__ bv)
{
    extern __shared__ __align__(128) char smraw[];
    int tid = threadIdx.x, lane = tid & 31, wid = tid >> 5;
    int n0 = blockIdx.x * 128, m0 = blockIdx.y * 128, which = blockIdx.z;
    int wmm = (wid >> 1) * 32, wnn = (wid & 1) * 64;
    int g = lane >> 2, tid4 = lane & 3;
    int quad = lane >> 3, qr = lane & 7;
    int aqrow = qr + 8 * (quad & 1), aqcol = 8 * (quad >> 1);

    const __half* Xp = g_Xh + (size_t)m0 * DIM;
    const __half* Wp = g_Wh[which] + (size_t)n0 * DIM;
    uint32_t sb = (uint32_t)__cvta_generic_to_shared(smraw);

    #pragma unroll
    for (int i = 0; i < 4; i++) {
        int idx = tid + i * 256;
        int row = idx >> 3, c8 = (idx & 7) * 8;
        CP_ASYNC16(sb + (row * PLD + c8) * 2,           &Xp[row * DIM + c8]);
        CP_ASYNC16(sb + STG_MAT + (row * PLD + c8) * 2, &Wp[row * DIM + c8]);
    }
    CP_COMMIT();

    float acc[2][8][4];
    #pragma unroll
    for (int i = 0; i < 2; i++)
        #pragma unroll
        for (int j = 0; j < 8; j++)
            #pragma unroll
            for (int t = 0; t < 4; t++) acc[i][j][t] = 0.f;

    for (int it = 0; it < DIM / 64; it++) {
        int cur = it & 1;
        uint32_t Ast = sb + cur * STG_B;
        uint32_t Bst = Ast + STG_MAT;

        CP_WAIT0();
        __syncthreads();

        if (it + 1 < DIM / 64) {
            int k0n = (it + 1) * 64;
            uint32_t nb = sb + (1 - cur) * STG_B;
            #pragma unroll
            for (int i = 0; i < 4; i++) {
                int idx = tid + i * 256;
                int row = idx >> 3, c8 = (idx & 7) * 8;
                CP_ASYNC16(nb + (row * PLD + c8) * 2,           &Xp[row * DIM + k0n + c8]);
                CP_ASYNC16(nb + STG_MAT + (row * PLD + c8) * 2, &Wp[row * DIM + k0n + c8]);
            }
            CP_COMMIT();
        }

        uint32_t qa[2][4][4];
        #pragma unroll
        for (int i = 0; i < 2; i++)
            #pragma unroll
            for (int kc = 0; kc < 4; kc++) {
                uint32_t addr = Ast + ((wmm + i * 16 + aqrow) * PLD + kc * 16 + aqcol) * 2;
                LDSM_X4(qa[i][kc][0], qa[i][kc][1], qa[i][kc][2], qa[i][kc][3], addr);
            }

        #pragma unroll
        for (int jp = 0; jp < 4; jp++) {
            #pragma unroll
            for (int kc = 0; kc < 4; kc++) {
                uint32_t b0, b1, b2, b3;
                uint32_t addr = Bst + ((wnn + (2 * jp + (quad >> 1)) * 8 + qr) * PLD
                                       + kc * 16 + 8 * (quad & 1)) * 2;
                LDSM_X4(b0, b1, b2, b3, addr);
                #pragma unroll
                for (int i = 0; i < 2; i++) {
                    MMA16816(acc[i][2*jp][0], acc[i][2*jp][1], acc[i][2*jp][2], acc[i][2*jp][3],
                             qa[i][kc][0], qa[i][kc][1], qa[i][kc][2], qa[i][kc][3], b0, b1);
                    MMA16816(acc[i][2*jp+1][0], acc[i][2*jp+1][1], acc[i][2*jp+1][2], acc[i][2*jp+1][3],
                             qa[i][kc][0], qa[i][kc][1], qa[i][kc][2], qa[i][kc][3], b2, b3);
                }
            }
        }
    }

    const float* bias = (which == 0) ? bq : (which == 1) ? bk : bv;
    __half* dstp = (which == 0) ? g_Qh : (which == 1) ? g_Kh : g_Vh;
    int h = (n0 + wnn) >> 6;

    #pragma unroll
    for (int i = 0; i < 2; i++) {
        #pragma unroll
        for (int rh = 0; rh < 2; rh++) {
            int m = m0 + wmm + i * 16 + g + rh * 8;
            int bb = m / SEQ, s = m % SEQ;
            size_t base = ((size_t)(bb * NH + h) * SEQ + s) * HD;
            #pragma unroll
            for (int j = 0; j < 4; j++) {
                int c0 = j * 8 + 2 * tid4;
                float y1[2], y2[2];
                #pragma unroll
                for (int e = 0; e < 2; e++) {
                    y1[e] = acc[i][j][rh * 2 + e]     + bias[n0 + wnn + c0 + e];
                    y2[e] = acc[i][j + 4][rh * 2 + e] + bias[n0 + wnn + c0 + 32 + e];
                }
                float o1[2], o2[2];
                if (which != 2) {
                    #pragma unroll
                    for (int e = 0; e < 2; e++) {
                        float sn = g_sin[s * DH + c0 + e], cs = g_cos[s * DH + c0 + e];
                        o1[e] = y1[e] * cs - y2[e] * sn;
                        o2[e] = y1[e] * sn + y2[e] * cs;
                    }
                    if (which == 0) {
                        #pragma unroll
                        for (int e = 0; e < 2; e++) { o1[e] *= QSCALE; o2[e] *= QSCALE; }
                    }
                } else {
                    o1[0] = y1[0]; o1[1] = y1[1];
                    o2[0] = y2[0]; o2[1] = y2[1];
                }
                __half2 v1, v2;
                v1.x = __float2half(o1[0]); v1.y = __float2half(o1[1]);
                v2.x = __float2half(o2[0]); v2.y = __float2half(o2[1]);
                *(__half2*)(dstp + base + c0)      = v1;
                *(__half2*)(dstp + base + c0 + 32) = v2;
            }
        }
    }
}

// ---------------------------------------------------------------------------
// Register-resident flash attention, 4 warps x 32 q-rows.
// Per 16-key chunk jp: S-MMAs -> ex2.approx.f16x2 (P directly as fp16 pairs)
// -> PV-MMAs for that chunk. No FMUL scaling (Q pre-scaled), pa is 8 regs.
// ---------------------------------------------------------------------------
#define TQ 128
#define NT (SEQ / 64)
#define ALD 72
#define OFF_Q  0
#define OFF_K0 (OFF_Q + TQ*ALD*2)          // 18432
#define OFF_K1 (OFF_K0 + 64*ALD*2)         // 27648
#define OFF_V0 (OFF_K1 + 64*ALD*2)         // 36864
#define OFF_V1 (OFF_V0 + 64*ALD*2)         // 46080
#define ATTN_SMEM (OFF_V1 + 64*ALD*2)      // 55296

__global__ __launch_bounds__(128) void attn_mma(float* __restrict__ out) {
    extern __shared__ __align__(128) char smraw[];
    __half* Qs = (__half*)(smraw + OFF_Q);

    int tid = threadIdx.x, lane = tid & 31, wid = tid >> 5;   // 4 warps
    int q0 = blockIdx.x * TQ, bh = blockIdx.y;
    int b = bh >> 4, h = bh & 15;
    int wq0 = wid * 32;
    int g = lane >> 2, tid4 = lane & 3;
    int quad = lane >> 3, qr = lane & 7;

    const __half* Qp = g_Qh + ((size_t)bh * SEQ + q0) * HD;
    const __half* Kp = g_Kh + (size_t)bh * SEQ * HD;
    const __half* Vp = g_Vh + (size_t)bh * SEQ * HD;

    uint32_t sb = (uint32_t)__cvta_generic_to_shared(smraw);

    #pragma unroll
    for (int i = 0; i < 8; i++) {
        int idx = tid + i * 128;
        int row = idx >> 3, c8 = (idx & 7) * 8;
        *(uint4*)&Qs[row * ALD + c8] = *(const uint4*)&Qp[row * HD + c8];
    }
    {
        int row = tid >> 3, c8 = (tid & 7) * 8;
        #pragma unroll
        for (int hf = 0; hf < 4; hf++) {
            int r = row + hf * 16;
            size_t gg = (size_t)r * HD + c8;
            CP_ASYNC16(sb + OFF_K0 + (r * ALD + c8) * 2, &Kp[gg]);
            CP_ASYNC16(sb + OFF_V0 + (r * ALD + c8) * 2, &Vp[gg]);
        }
        CP_COMMIT();
    }
    __syncthreads();

    uint32_t qa[2][4][4];
    {
        int aqrow = qr + 8 * (quad & 1), aqcol = 8 * (quad >> 1);
        #pragma unroll
        for (int i = 0; i < 2; i++)
            #pragma unroll
            for (int kc = 0; kc < 4; kc++) {
                uint32_t addr = sb + OFF_Q + ((wq0 + i * 16 + aqrow) * ALD + kc * 16 + aqcol) * 2;
                LDSM_X4(qa[i][kc][0], qa[i][kc][1], qa[i][kc][2], qa[i][kc][3], addr);
            }
    }

    float ctx[2][8][4];
    #pragma unroll
    for (int i = 0; i < 2; i++)
        #pragma unroll
        for (int j = 0; j < 8; j++)
            #pragma unroll
            for (int t = 0; t < 4; t++) ctx[i][j][t] = 0.f;
    float rs[2][2] = {{0.f, 0.f}, {0.f, 0.f}};

    for (int kt = 0; kt < NT; kt++) {
        int cur = kt & 1;
        uint32_t Kc = sb + (cur ? OFF_K1 : OFF_K0);
        uint32_t Vc = sb + (cur ? OFF_V1 : OFF_V0);

        CP_WAIT0();
        __syncthreads();

        if (kt + 1 < NT) {
            uint32_t kb = sb + ((1 - cur) ? OFF_K1 : OFF_K0);
            uint32_t vb = sb + ((1 - cur) ? OFF_V1 : OFF_V0);
            int row = tid >> 3, c8 = (tid & 7) * 8;
            #pragma unroll
            for (int hf = 0; hf < 4; hf++) {
                int r = row + hf * 16;
                size_t gg = (size_t)((kt + 1) * 64 + r) * HD + c8;
                CP_ASYNC16(kb + (r * ALD + c8) * 2, &Kp[gg]);
                CP_ASYNC16(vb + (r * ALD + c8) * 2, &Vp[gg]);
            }
            CP_COMMIT();
        }

        // per 16-key chunk: S -> ex2 -> PV
        #pragma unroll
        for (int jp = 0; jp < 4; jp++) {
            float ca[2][2][4];
            #pragma unroll
            for (int i = 0; i < 2; i++)
                #pragma unroll
                for (int t2 = 0; t2 < 2; t2++)
                    #pragma unroll
                    for (int t = 0; t < 4; t++) ca[i][t2][t] = 0.f;
            #pragma unroll
            for (int kc = 0; kc < 4; kc++) {
                uint32_t b0, b1, b2, b3;
                uint32_t addr = Kc + (((2 * jp + (quad >> 1)) * 8 + qr) * ALD
                                      + kc * 16 + 8 * (quad & 1)) * 2;
                LDSM_X4(b0, b1, b2, b3, addr);
                #pragma unroll
                for (int i = 0; i < 2; i++) {
                    MMA16816(ca[i][0][0], ca[i][0][1], ca[i][0][2], ca[i][0][3],
                             qa[i][kc][0], qa[i][kc][1], qa[i][kc][2], qa[i][kc][3], b0, b1);
                    MMA16816(ca[i][1][0], ca[i][1][1], ca[i][1][2], ca[i][1][3],
                             qa[i][kc][0], qa[i][kc][1], qa[i][kc][2], qa[i][kc][3], b2, b3);
                }
            }
            // exp2 in fp16x2 — result IS the P fragment
            uint32_t pl[2][2][2];
            #pragma unroll
            for (int i = 0; i < 2; i++)
                #pragma unroll
                for (int t2 = 0; t2 < 2; t2++) {
                    uint32_t lo_in = pack_h2(ca[i][t2][0], ca[i][t2][1]);
                    uint32_t hi_in = pack_h2(ca[i][t2][2], ca[i][t2][3]);
                    EX2_H2(pl[i][t2][0], lo_in);
                    EX2_H2(pl[i][t2][1], hi_in);
                    float2 flo = h2_to_f2(pl[i][t2][0]);
                    float2 fhi = h2_to_f2(pl[i][t2][1]);
                    rs[i][0] += flo.x + flo.y;
                    rs[i][1] += fhi.x + fhi.y;
                }
            // PV for this 16-key chunk
            #pragma unroll
            for (int jp2 = 0; jp2 < 4; jp2++) {
                uint32_t b0, b1, b2, b3;
                uint32_t addr = Vc + ((jp * 16 + 8 * (quad & 1) + qr) * ALD
                                      + (2 * jp2 + (quad >> 1)) * 8) * 2;
                LDSM_X4_T(b0, b1, b2, b3, addr);
                #pragma unroll
                for (int i = 0; i < 2; i++) {
                    MMA16816(ctx[i][2*jp2][0], ctx[i][2*jp2][1], ctx[i][2*jp2][2], ctx[i][2*jp2][3],
                             pl[i][0][0], pl[i][0][1], pl[i][1][0], pl[i][1][1], b0, b1);
                    MMA16816(ctx[i][2*jp2+1][0], ctx[i][2*jp2+1][1], ctx[i][2*jp2+1][2], ctx[i][2*jp2+1][3],
                             pl[i][0][0], pl[i][0][1], pl[i][1][0], pl[i][1][1], b2, b3);
                }
            }
        }
    }

    #pragma unroll
    for (int i = 0; i < 2; i++) {
        rs[i][0] += __shfl_xor_sync(0xffffffffu, rs[i][0], 1);
        rs[i][0] += __shfl_xor_sync(0xffffffffu, rs[i][0], 2);
        rs[i][1] += __shfl_xor_sync(0xffffffffu, rs[i][1], 1);
        rs[i][1] += __shfl_xor_sync(0xffffffffu, rs[i][1], 2);
        float inv0 = 1.f / rs[i][0], inv1 = 1.f / rs[i][1];

        int s0 = q0 + wq0 + i * 16 + g, s1 = s0 + 8;
        float* o0 = out + ((size_t)b * SEQ + s0) * DIM + h * HD + 2 * tid4;
        float* o1 = out + ((size_t)b * SEQ + s1) * DIM + h * HD + 2 * tid4;
        #pragma unroll
        for (int j2 = 0; j2 < 8; j2++) {
            float2 v0 = make_float2(ctx[i][j2][0] * inv0, ctx[i][j2][1] * inv0);
            float2 v1 = make_float2(ctx[i][j2][2] * inv1, ctx[i][j2][3] * inv1);
            *(float2*)(o0 + j2 * 8) = v0;
            *(float2*)(o1 + j2 * 8) = v1;
        }
    }
}

// ---------------------------------------------------------------------------
extern "C" void kernel_launch(void* const* d_in, const int* in_sizes, int n_in,
                              void* d_out, int out_size) {
    const float* X  = (const float*)d_in[0];
    const float* Wq = (const float*)d_in[1];
    const float* bq = (const float*)d_in[2];
    const float* Wk = (const float*)d_in[3];
    const float* bk = (const float*)d_in[4];
    const float* Wv = (const float*)d_in[5];
    const float* bv = (const float*)d_in[6];
    float* out = (float*)d_out;

    rope_table_kernel<<<(SEQ * DH + 255) / 256, 256>>>();

    int ntot = NX2 + 3 * NW2;
    convert_all<<<(ntot + 255) / 256, 256>>>(X, Wq, Wk, Wv);

    cudaFuncSetAttribute(gemm_mma, cudaFuncAttributeMaxDynamicSharedMemorySize, PROJ_SMEM);
    dim3 ggrid(DIM / 128, MTOT / 128, 3);
    gemm_mma<<<ggrid, 256, PROJ_SMEM>>>(bq, bk, bv);

    cudaFuncSetAttribute(attn_mma, cudaFuncAttributeMaxDynamicSharedMemorySize, ATTN_SMEM);
    dim3 agrid(SEQ / TQ, BATCH * NH);
    attn_mma<<<agrid, 128, ATTN_SMEM>>>(out);
}

// round 17
// speedup vs baseline: 1.6345x; 1.0241x over previous
#include <cuda_runtime.h>
#include <cuda_fp16.h>
#include <math.h>
#include <stdint.h>

#define BATCH 2
#define SEQ 2048
#define DIM 1024
#define NH 16
#define HD 64
#define DH 32
#define MTOT (BATCH*SEQ)   // 4096
#define QSCALE 0.1803368801111204f   // (1/sqrt(64)) * log2(e)
#define H2_ONES 0x3C003C00u          // {1.0h, 1.0h}

// ---------------- device scratch (no allocation allowed) -------------------
__device__ float g_sin[SEQ*DH], g_cos[SEQ*DH];
__device__ __half g_Xh[MTOT*DIM];
__device__ __half g_Wh[3][DIM*DIM];
__device__ __half g_Qh[MTOT*DIM];
__device__ __half g_Kh[MTOT*DIM];
__device__ __half g_Vh[MTOT*DIM];

// ---------------- PTX helpers ----------------------------------------------
#define CP_ASYNC16(dst_u32, src_ptr) \
    asm volatile("cp.async.cg.shared.global [%0], [%1], 16;" \
                 :: "r"(dst_u32), "l"(src_ptr) : "memory")
#define CP_COMMIT() asm volatile("cp.async.commit_group;" ::: "memory")
#define CP_WAIT0()  asm volatile("cp.async.wait_group 0;" ::: "memory")

#define LDSM_X4(r0, r1, r2, r3, addr) \
    asm volatile("ldmatrix.sync.aligned.m8n8.x4.shared.b16 {%0,%1,%2,%3}, [%4];" \
                 : "=r"(r0), "=r"(r1), "=r"(r2), "=r"(r3) : "r"(addr))
#define LDSM_X4_T(r0, r1, r2, r3, addr) \
    asm volatile("ldmatrix.sync.aligned.m8n8.x4.trans.shared.b16 {%0,%1,%2,%3}, [%4];" \
                 : "=r"(r0), "=r"(r1), "=r"(r2), "=r"(r3) : "r"(addr))
#define MMA16816(c0, c1, c2, c3, a0, a1, a2, a3, b0, b1) \
    asm volatile("mma.sync.aligned.m16n8k16.row.col.f32.f16.f16.f32 " \
                 "{%0,%1,%2,%3}, {%4,%5,%6,%7}, {%8,%9}, {%0,%1,%2,%3};" \
                 : "+f"(c0), "+f"(c1), "+f"(c2), "+f"(c3) \
                 : "r"(a0), "r"(a1), "r"(a2), "r"(a3), "r"(b0), "r"(b1))
#define EX2_H2(dst, src) \
    asm("ex2.approx.f16x2 %0, %1;" : "=r"(dst) : "r"(src))

__device__ __forceinline__ uint32_t pack_h2(float a, float b) {
    __half2 t = __floats2half2_rn(a, b);
    return *(uint32_t*)&t;
}

// ---------------------------------------------------------------------------
// RoPE tables in double precision
// ---------------------------------------------------------------------------
__global__ void rope_table_kernel() {
    int idx = blockIdx.x * blockDim.x + threadIdx.x;
    if (idx >= SEQ * DH) return;
    int s = idx / DH, i = idx % DH;
    double ang = (double)s * pow(10000.0, -((double)i) / (double)DH);
    g_sin[idx] = (float)sin(ang);
    g_cos[idx] = (float)cos(ang);
}

// ---------------------------------------------------------------------------
// Fused conversion: X and all three W -> fp16, one launch.
// ---------------------------------------------------------------------------
#define NX2 (MTOT*DIM/2)
#define NW2 (DIM*DIM/2)
__global__ void convert_all(const float* __restrict__ X,
                            const float* __restrict__ Wq,
                            const float* __restrict__ Wk,
                            const float* __restrict__ Wv) {
    int i = blockIdx.x * blockDim.x + threadIdx.x;
    const float* src;
    __half* dst;
    int off;
    if (i < NX2)               { src = X;  dst = g_Xh;    off = i; }
    else if (i < NX2 + NW2)    { src = Wq; dst = g_Wh[0]; off = i - NX2; }
    else if (i < NX2 + 2*NW2)  { src = Wk; dst = g_Wh[1]; off = i - NX2 - NW2; }
    else if (i < NX2 + 3*NW2)  { src = Wv; dst = g_Wh[2]; off = i - NX2 - 2*NW2; }
    else return;
    float2 x = ((const float2*)src)[off];
    __half2 hh;
    hh.x = __float2half(x.x);
    hh.y = __float2half(x.y);
    ((__half2*)dst)[off] = hh;
}

// ---------------------------------------------------------------------------
// Raw mma.sync GEMM + IN-REGISTER epilogue.
// Q is pre-scaled by QSCALE so attention scores land in the exp2 domain.
// ---------------------------------------------------------------------------
#define PLD 72
#define STG_MAT (128 * PLD * 2)       // 18432 per matrix
#define STG_B   (2 * STG_MAT)         // 36864 per stage (A+B)
#define PROJ_SMEM (2 * STG_B)         // 73728

__global__ __launch_bounds__(256) void gemm_mma(
    const float* __restrict__ bq, const float* __restrict__ bk,
    const float* __restrict__ bv)
{
    extern __shared__ __align__(128) char smraw[];
    int tid = threadIdx.x, lane = tid & 31, wid = tid >> 5;
    int n0 = blockIdx.x * 128, m0 = blockIdx.y * 128, which = blockIdx.z;
    int wmm = (wid >> 1) * 32, wnn = (wid & 1) * 64;
    int g = lane >> 2, tid4 = lane & 3;
    int quad = lane >> 3, qr = lane & 7;
    int aqrow = qr + 8 * (quad & 1), aqcol = 8 * (quad >> 1);

    const __half* Xp = g_Xh + (size_t)m0 * DIM;
    const __half* Wp = g_Wh[which] + (size_t)n0 * DIM;
    uint32_t sb = (uint32_t)__cvta_generic_to_shared(smraw);

    #pragma unroll
    for (int i = 0; i < 4; i++) {
        int idx = tid + i * 256;
        int row = idx >> 3, c8 = (idx & 7) * 8;
        CP_ASYNC16(sb + (row * PLD + c8) * 2,           &Xp[row * DIM + c8]);
        CP_ASYNC16(sb + STG_MAT + (row * PLD + c8) * 2, &Wp[row * DIM + c8]);
    }
    CP_COMMIT();

    float acc[2][8][4];
    #pragma unroll
    for (int i = 0; i < 2; i++)
        #pragma unroll
        for (int j = 0; j < 8; j++)
            #pragma unroll
            for (int t = 0; t < 4; t++) acc[i][j][t] = 0.f;

    for (int it = 0; it < DIM / 64; it++) {
        int cur = it & 1;
        uint32_t Ast = sb + cur * STG_B;
        uint32_t Bst = Ast + STG_MAT;

        CP_WAIT0();
        __syncthreads();

        if (it + 1 < DIM / 64) {
            int k0n = (it + 1) * 64;
            uint32_t nb = sb + (1 - cur) * STG_B;
            #pragma unroll
            for (int i = 0; i < 4; i++) {
                int idx = tid + i * 256;
                int row = idx >> 3, c8 = (idx & 7) * 8;
                CP_ASYNC16(nb + (row * PLD + c8) * 2,           &Xp[row * DIM + k0n + c8]);
                CP_ASYNC16(nb + STG_MAT + (row * PLD + c8) * 2, &Wp[row * DIM + k0n + c8]);
            }
            CP_COMMIT();
        }

        uint32_t qa[2][4][4];
        #pragma unroll
        for (int i = 0; i < 2; i++)
            #pragma unroll
            for (int kc = 0; kc < 4; kc++) {
                uint32_t addr = Ast + ((wmm + i * 16 + aqrow) * PLD + kc * 16 + aqcol) * 2;
                LDSM_X4(qa[i][kc][0], qa[i][kc][1], qa[i][kc][2], qa[i][kc][3], addr);
            }

        #pragma unroll
        for (int jp = 0; jp < 4; jp++) {
            #pragma unroll
            for (int kc = 0; kc < 4; kc++) {
                uint32_t b0, b1, b2, b3;
                uint32_t addr = Bst + ((wnn + (2 * jp + (quad >> 1)) * 8 + qr) * PLD
                                       + kc * 16 + 8 * (quad & 1)) * 2;
                LDSM_X4(b0, b1, b2, b3, addr);
                #pragma unroll
                for (int i = 0; i < 2; i++) {
                    MMA16816(acc[i][2*jp][0], acc[i][2*jp][1], acc[i][2*jp][2], acc[i][2*jp][3],
                             qa[i][kc][0], qa[i][kc][1], qa[i][kc][2], qa[i][kc][3], b0, b1);
                    MMA16816(acc[i][2*jp+1][0], acc[i][2*jp+1][1], acc[i][2*jp+1][2], acc[i][2*jp+1][3],
                             qa[i][kc][0], qa[i][kc][1], qa[i][kc][2], qa[i][kc][3], b2, b3);
                }
            }
        }
    }

    const float* bias = (which == 0) ? bq : (which == 1) ? bk : bv;
    __half* dstp = (which == 0) ? g_Qh : (which == 1) ? g_Kh : g_Vh;
    int h = (n0 + wnn) >> 6;

    #pragma unroll
    for (int i = 0; i < 2; i++) {
        #pragma unroll
        for (int rh = 0; rh < 2; rh++) {
            int m = m0 + wmm + i * 16 + g + rh * 8;
            int bb = m / SEQ, s = m % SEQ;
            size_t base = ((size_t)(bb * NH + h) * SEQ + s) * HD;
            #pragma unroll
            for (int j = 0; j < 4; j++) {
                int c0 = j * 8 + 2 * tid4;
                float y1[2], y2[2];
                #pragma unroll
                for (int e = 0; e < 2; e++) {
                    y1[e] = acc[i][j][rh * 2 + e]     + bias[n0 + wnn + c0 + e];
                    y2[e] = acc[i][j + 4][rh * 2 + e] + bias[n0 + wnn + c0 + 32 + e];
                }
                float o1[2], o2[2];
                if (which != 2) {
                    #pragma unroll
                    for (int e = 0; e < 2; e++) {
                        float sn = g_sin[s * DH + c0 + e], cs = g_cos[s * DH + c0 + e];
                        o1[e] = y1[e] * cs - y2[e] * sn;
                        o2[e] = y1[e] * sn + y2[e] * cs;
                    }
                    if (which == 0) {
                        #pragma unroll
                        for (int e = 0; e < 2; e++) { o1[e] *= QSCALE; o2[e] *= QSCALE; }
                    }
                } else {
                    o1[0] = y1[0]; o1[1] = y1[1];
                    o2[0] = y2[0]; o2[1] = y2[1];
                }
                __half2 v1, v2;
                v1.x = __float2half(o1[0]); v1.y = __float2half(o1[1]);
                v2.x = __float2half(o2[0]); v2.y = __float2half(o2[1]);
                *(__half2*)(dstp + base + c0)      = v1;
                *(__half2*)(dstp + base + c0 + 32) = v2;
            }
        }
    }
}

// ---------------------------------------------------------------------------
// Register-resident flash attention, 4 warps x 32 q-rows.
// S-MMAs -> ex2.approx.f16x2 -> PV-MMAs per 16-key chunk.
// ROW SUMS VIA TENSOR PIPE: extra mma with B = ones (constant fragment) —
// removes all cvt/add row-sum bookkeeping AND the final shuffles.
// ---------------------------------------------------------------------------
#define TQ 128
#define NT (SEQ / 64)
#define ALD 72
#define OFF_Q  0
#define OFF_K0 (OFF_Q + TQ*ALD*2)          // 18432
#define OFF_K1 (OFF_K0 + 64*ALD*2)         // 27648
#define OFF_V0 (OFF_K1 + 64*ALD*2)         // 36864
#define OFF_V1 (OFF_V0 + 64*ALD*2)         // 46080
#define ATTN_SMEM (OFF_V1 + 64*ALD*2)      // 55296

__global__ __launch_bounds__(128) void attn_mma(float* __restrict__ out) {
    extern __shared__ __align__(128) char smraw[];
    __half* Qs = (__half*)(smraw + OFF_Q);

    int tid = threadIdx.x, lane = tid & 31, wid = tid >> 5;   // 4 warps
    int q0 = blockIdx.x * TQ, bh = blockIdx.y;
    int b = bh >> 4, h = bh & 15;
    int wq0 = wid * 32;
    int g = lane >> 2, tid4 = lane & 3;
    int quad = lane >> 3, qr = lane & 7;

    const __half* Qp = g_Qh + ((size_t)bh * SEQ + q0) * HD;
    const __half* Kp = g_Kh + (size_t)bh * SEQ * HD;
    const __half* Vp = g_Vh + (size_t)bh * SEQ * HD;

    uint32_t sb = (uint32_t)__cvta_generic_to_shared(smraw);

    #pragma unroll
    for (int i = 0; i < 8; i++) {
        int idx = tid + i * 128;
        int row = idx >> 3, c8 = (idx & 7) * 8;
        *(uint4*)&Qs[row * ALD + c8] = *(const uint4*)&Qp[row * HD + c8];
    }
    {
        int row = tid >> 3, c8 = (tid & 7) * 8;
        #pragma unroll
        for (int hf = 0; hf < 4; hf++) {
            int r = row + hf * 16;
            size_t gg = (size_t)r * HD + c8;
            CP_ASYNC16(sb + OFF_K0 + (r * ALD + c8) * 2, &Kp[gg]);
            CP_ASYNC16(sb + OFF_V0 + (r * ALD + c8) * 2, &Vp[gg]);
        }
        CP_COMMIT();
    }
    __syncthreads();

    uint32_t qa[2][4][4];
    {
        int aqrow = qr + 8 * (quad & 1), aqcol = 8 * (quad >> 1);
        #pragma unroll
        for (int i = 0; i < 2; i++)
            #pragma unroll
            for (int kc = 0; kc < 4; kc++) {
                uint32_t addr = sb + OFF_Q + ((wq0 + i * 16 + aqrow) * ALD + kc * 16 + aqcol) * 2;
                LDSM_X4(qa[i][kc][0], qa[i][kc][1], qa[i][kc][2], qa[i][kc][3], addr);
            }
    }

    float ctx[2][8][4];
    #pragma unroll
    for (int i = 0; i < 2; i++)
        #pragma unroll
        for (int j = 0; j < 8; j++)
            #pragma unroll
            for (int t = 0; t < 4; t++) ctx[i][j][t] = 0.f;
    float rsacc[2][4];
    #pragma unroll
    for (int i = 0; i < 2; i++)
        #pragma unroll
        for (int t = 0; t < 4; t++) rsacc[i][t] = 0.f;

    for (int kt = 0; kt < NT; kt++) {
        int cur = kt & 1;
        uint32_t Kc = sb + (cur ? OFF_K1 : OFF_K0);
        uint32_t Vc = sb + (cur ? OFF_V1 : OFF_V0);

        CP_WAIT0();
        __syncthreads();

        if (kt + 1 < NT) {
            uint32_t kb = sb + ((1 - cur) ? OFF_K1 : OFF_K0);
            uint32_t vb = sb + ((1 - cur) ? OFF_V1 : OFF_V0);
            int row = tid >> 3, c8 = (tid & 7) * 8;
            #pragma unroll
            for (int hf = 0; hf < 4; hf++) {
                int r = row + hf * 16;
                size_t gg = (size_t)((kt + 1) * 64 + r) * HD + c8;
                CP_ASYNC16(kb + (r * ALD + c8) * 2, &Kp[gg]);
                CP_ASYNC16(vb + (r * ALD + c8) * 2, &Vp[gg]);
            }
            CP_COMMIT();
        }

        // per 16-key chunk: S -> ex2 -> row-sum MMA + PV MMAs
        #pragma unroll
        for (int jp = 0; jp < 4; jp++) {
            float ca[2][2][4];
            #pragma unroll
            for (int i = 0; i < 2; i++)
                #pragma unroll
                for (int t2 = 0; t2 < 2; t2++)
                    #pragma unroll
                    for (int t = 0; t < 4; t++) ca[i][t2][t] = 0.f;
            #pragma unroll
            for (int kc = 0; kc < 4; kc++) {
                uint32_t b0, b1, b2, b3;
                uint32_t addr = Kc + (((2 * jp + (quad >> 1)) * 8 + qr) * ALD
                                      + kc * 16 + 8 * (quad & 1)) * 2;
                LDSM_X4(b0, b1, b2, b3, addr);
                #pragma unroll
                for (int i = 0; i < 2; i++) {
                    MMA16816(ca[i][0][0], ca[i][0][1], ca[i][0][2], ca[i][0][3],
                             qa[i][kc][0], qa[i][kc][1], qa[i][kc][2], qa[i][kc][3], b0, b1);
                    MMA16816(ca[i][1][0], ca[i][1][1], ca[i][1][2], ca[i][1][3],
                             qa[i][kc][0], qa[i][kc][1], qa[i][kc][2], qa[i][kc][3], b2, b3);
                }
            }
            // exp2 in fp16x2 — result IS the P fragment
            uint32_t pl[2][2][2];
            #pragma unroll
            for (int i = 0; i < 2; i++) {
                #pragma unroll
                for (int t2 = 0; t2 < 2; t2++) {
                    uint32_t lo_in = pack_h2(ca[i][t2][0], ca[i][t2][1]);
                    uint32_t hi_in = pack_h2(ca[i][t2][2], ca[i][t2][3]);
                    EX2_H2(pl[i][t2][0], lo_in);
                    EX2_H2(pl[i][t2][1], hi_in);
                }
                // row sums on the tensor pipe: P . ones
                MMA16816(rsacc[i][0], rsacc[i][1], rsacc[i][2], rsacc[i][3],
                         pl[i][0][0], pl[i][0][1], pl[i][1][0], pl[i][1][1],
                         H2_ONES, H2_ONES);
            }
            // PV for this 16-key chunk
            #pragma unroll
            for (int jp2 = 0; jp2 < 4; jp2++) {
                uint32_t b0, b1, b2, b3;
                uint32_t addr = Vc + ((jp * 16 + 8 * (quad & 1) + qr) * ALD
                                      + (2 * jp2 + (quad >> 1)) * 8) * 2;
                LDSM_X4_T(b0, b1, b2, b3, addr);
                #pragma unroll
                for (int i = 0; i < 2; i++) {
                    MMA16816(ctx[i][2*jp2][0], ctx[i][2*jp2][1], ctx[i][2*jp2][2], ctx[i][2*jp2][3],
                             pl[i][0][0], pl[i][0][1], pl[i][1][0], pl[i][1][1], b0, b1);
                    MMA16816(ctx[i][2*jp2+1][0], ctx[i][2*jp2+1][1], ctx[i][2*jp2+1][2], ctx[i][2*jp2+1][3],
                             pl[i][0][0], pl[i][0][1], pl[i][1][0], pl[i][1][1], b2, b3);
                }
            }
        }
    }

    // rsacc[i][0] = rowsum(rows g), rsacc[i][2] = rowsum(rows g+8) — already
    // fully reduced across lanes by the MMA; no shuffles needed.
    #pragma unroll
    for (int i = 0; i < 2; i++) {
        float inv0 = 1.f / rsacc[i][0], inv1 = 1.f / rsacc[i][2];

        int s0 = q0 + wq0 + i * 16 + g, s1 = s0 + 8;
        float* o0 = out + ((size_t)b * SEQ + s0) * DIM + h * HD + 2 * tid4;
        float* o1 = out + ((size_t)b * SEQ + s1) * DIM + h * HD + 2 * tid4;
        #pragma unroll
        for (int j2 = 0; j2 < 8; j2++) {
            float2 v0 = make_float2(ctx[i][j2][0] * inv0, ctx[i][j2][1] * inv0);
            float2 v1 = make_float2(ctx[i][j2][2] * inv1, ctx[i][j2][3] * inv1);
            *(float2*)(o0 + j2 * 8) = v0;
            *(float2*)(o1 + j2 * 8) = v1;
        }
    }
}

// ---------------------------------------------------------------------------
extern "C" void kernel_launch(void* const* d_in, const int* in_sizes, int n_in,
                              void* d_out, int out_size) {
    const float* X  = (const float*)d_in[0];
    const float* Wq = (const float*)d_in[1];
    const float* bq = (const float*)d_in[2];
    const float* Wk = (const float*)d_in[3];
    const float* bk = (const float*)d_in[4];
    const float* Wv = (const float*)d_in[5];
    const float* bv = (const float*)d_in[6];
    float* out = (float*)d_out;

    rope_table_kernel<<<(SEQ * DH + 255) / 256, 256>>>();

    int ntot = NX2 + 3 * NW2;
    convert_all<<<(ntot + 255) / 256, 256>>>(X, Wq, Wk, Wv);

    cudaFuncSetAttribute(gemm_mma, cudaFuncAttributeMaxDynamicSharedMemorySize, PROJ_SMEM);
    dim3 ggrid(DIM / 128, MTOT / 128, 3);
    gemm_mma<<<ggrid, 256, PROJ_SMEM>>>(bq, bk, bv);

    cudaFuncSetAttribute(attn_mma, cudaFuncAttributeMaxDynamicSharedMemorySize, ATTN_SMEM);
    dim3 agrid(SEQ / TQ, BATCH * NH);
    attn_mma<<<agrid, 128, ATTN_SMEM>>>(out);
}